// round 1
// baseline (speedup 1.0000x reference)
#include <cuda_runtime.h>
#include <stdint.h>

// Problem constants (fixed by reference)
#define NN   50000      // nodes
#define NE   800000     // edges (before self loops)
#define NET  850000     // edges + self loops
#define ICH  128        // in channels
#define HC   256        // heads * out = 4*64
#define OC   64         // out channels
#define NH   4          // heads

// ---------------- device scratch (allocation-free) ----------------
__device__ float g_x[(size_t)NN * HC];      // projected features [N, H*C]
__device__ float g_asrc[NN * NH];           // per-node src logits
__device__ float g_adst[NN * NH];           // per-node dst logits
__device__ float g_ex[(size_t)NET * NH];    // per-edge exp(alpha)
__device__ float g_denom[NN * NH];          // softmax denominators
__device__ int   g_is64;                    // edge_index dtype flag

// ---------------- dtype detection -------------------------------
// If edge_index is int64 (little-endian, values in [0, 50000)), every odd
// 32-bit word of the first 2048 entries is zero. If int32, those words are
// random node ids -> practically impossible to all be zero.
__global__ void detect_kernel(const int* __restrict__ idx32) {
    __shared__ int bad;
    if (threadIdx.x == 0) bad = 0;
    __syncthreads();
    for (int i = threadIdx.x; i < 2048; i += blockDim.x) {
        if (idx32[2 * i + 1] != 0) bad = 1;
    }
    __syncthreads();
    if (threadIdx.x == 0) g_is64 = bad ? 0 : 1;
}

// ---------------- init: out = bias (broadcast), denom = 0 --------
__global__ void init_kernel(float* __restrict__ out, const float* __restrict__ bias) {
    int i = blockIdx.x * blockDim.x + threadIdx.x;
    if (i < NN * OC) out[i] = bias[i & (OC - 1)];
    if (i < NN * NH) g_denom[i] = 0.0f;
}

// ---------------- GEMM: g_x = feature[N,128] @ lin_w[128,256] ----
// Tiled SIMT fp32: BM=BN=64, BK=16, 256 threads, 4x4 per thread.
__global__ void __launch_bounds__(256) gemm_kernel(const float* __restrict__ A,
                                                   const float* __restrict__ B) {
    __shared__ float As[16][64];   // k-major A tile
    __shared__ float Bs[16][64];
    const int bm = blockIdx.x * 64;
    const int bn = blockIdx.y * 64;
    const int t  = threadIdx.x;
    const int ty = t >> 4;          // 0..15 -> M sub-tile
    const int tx = t & 15;          // 0..15 -> N sub-tile

    const int ar = t >> 2;          // A load: row 0..63
    const int ac = (t & 3) * 4;     // A load: k 0..12 step 4
    const int br = t >> 4;          // B load: k 0..15
    const int bc = (t & 15) * 4;    // B load: col 0..60 step 4

    float acc[4][4] = {};

    for (int k0 = 0; k0 < ICH; k0 += 16) {
        float4 av;
        if (bm + ar < NN)
            av = *(const float4*)&A[(size_t)(bm + ar) * ICH + k0 + ac];
        else
            av = make_float4(0.f, 0.f, 0.f, 0.f);
        As[ac + 0][ar] = av.x;
        As[ac + 1][ar] = av.y;
        As[ac + 2][ar] = av.z;
        As[ac + 3][ar] = av.w;

        *(float4*)&Bs[br][bc] = *(const float4*)&B[(size_t)(k0 + br) * HC + bn + bc];
        __syncthreads();

#pragma unroll
        for (int k = 0; k < 16; k++) {
            float a0 = As[k][ty * 4 + 0];
            float a1 = As[k][ty * 4 + 1];
            float a2 = As[k][ty * 4 + 2];
            float a3 = As[k][ty * 4 + 3];
            float b0 = Bs[k][tx * 4 + 0];
            float b1 = Bs[k][tx * 4 + 1];
            float b2 = Bs[k][tx * 4 + 2];
            float b3 = Bs[k][tx * 4 + 3];
            acc[0][0] += a0 * b0; acc[0][1] += a0 * b1; acc[0][2] += a0 * b2; acc[0][3] += a0 * b3;
            acc[1][0] += a1 * b0; acc[1][1] += a1 * b1; acc[1][2] += a1 * b2; acc[1][3] += a1 * b3;
            acc[2][0] += a2 * b0; acc[2][1] += a2 * b1; acc[2][2] += a2 * b2; acc[2][3] += a2 * b3;
            acc[3][0] += a3 * b0; acc[3][1] += a3 * b1; acc[3][2] += a3 * b2; acc[3][3] += a3 * b3;
        }
        __syncthreads();
    }

#pragma unroll
    for (int i = 0; i < 4; i++) {
        int row = bm + ty * 4 + i;
        if (row < NN) {
            float4 v = make_float4(acc[i][0], acc[i][1], acc[i][2], acc[i][3]);
            *(float4*)&g_x[(size_t)row * HC + bn + tx * 4] = v;
        }
    }
}

// ---------------- per-node attention logits ----------------------
// thread per (node, head): a = sum_c x[n,h,c] * att[h,c]
__global__ void logits_kernel(const float* __restrict__ att_s,
                              const float* __restrict__ att_d) {
    int i = blockIdx.x * blockDim.x + threadIdx.x;
    if (i >= NN * NH) return;
    int n = i >> 2, h = i & 3;
    const float* xr = &g_x[(size_t)n * HC + h * OC];
    const float* as = &att_s[h * OC];
    const float* ad = &att_d[h * OC];
    float s = 0.f, d = 0.f;
#pragma unroll 16
    for (int c = 0; c < OC; c++) {
        float v = xr[c];
        s += v * as[c];
        d += v * ad[c];
    }
    g_asrc[i] = s;
    g_adst[i] = d;
}

// ---------------- edge pass: exp(leaky_relu(logit)), denom accum --
__global__ void edge_kernel(const void* __restrict__ idx) {
    int e = blockIdx.x * blockDim.x + threadIdx.x;
    if (e >= NET) return;
    int src, dst;
    if (e < NE) {
        if (g_is64) {
            const long long* p = (const long long*)idx;
            src = (int)p[e];
            dst = (int)p[NE + e];
        } else {
            const int* p = (const int*)idx;
            src = p[e];
            dst = p[NE + e];
        }
    } else {
        src = dst = e - NE;
    }
    float4 as = *(const float4*)&g_asrc[src * NH];
    float4 ad = *(const float4*)&g_adst[dst * NH];
    float al[4] = { as.x + ad.x, as.y + ad.y, as.z + ad.z, as.w + ad.w };
    float ex[4];
#pragma unroll
    for (int h = 0; h < 4; h++) {
        float v = al[h];
        v = v > 0.f ? v : 0.2f * v;        // leaky_relu, slope 0.2
        ex[h] = __expf(v);                  // no max-shift: |v| <= ~8, safe in fp32
        atomicAdd(&g_denom[dst * NH + h], ex[h]);
    }
    *(float4*)&g_ex[(size_t)e * NH] = make_float4(ex[0], ex[1], ex[2], ex[3]);
}

// ---------------- scatter: out[dst,c] += sum_h w_h * x[src,h,c] / 4 ----
// one warp per edge; lane handles channels c and c+32.
__global__ void __launch_bounds__(256) scatter_kernel(const void* __restrict__ idx,
                                                      float* __restrict__ out) {
    int gtid = blockIdx.x * blockDim.x + threadIdx.x;
    int e    = gtid >> 5;
    int lane = threadIdx.x & 31;
    if (e >= NET) return;

    int src, dst;
    if (e < NE) {
        if (g_is64) {
            const long long* p = (const long long*)idx;
            src = (int)p[e];
            dst = (int)p[NE + e];
        } else {
            const int* p = (const int*)idx;
            src = p[e];
            dst = p[NE + e];
        }
    } else {
        src = dst = e - NE;
    }

    float w = 0.f;
    if (lane < 4)
        w = g_ex[(size_t)e * NH + lane] / g_denom[dst * NH + lane] * 0.25f;
    float w0 = __shfl_sync(0xffffffffu, w, 0);
    float w1 = __shfl_sync(0xffffffffu, w, 1);
    float w2 = __shfl_sync(0xffffffffu, w, 2);
    float w3 = __shfl_sync(0xffffffffu, w, 3);

    const float* xr = &g_x[(size_t)src * HC];
    float acc0 = w0 * xr[lane]       + w1 * xr[64 + lane]
               + w2 * xr[128 + lane] + w3 * xr[192 + lane];
    float acc1 = w0 * xr[32 + lane]  + w1 * xr[96 + lane]
               + w2 * xr[160 + lane] + w3 * xr[224 + lane];

    atomicAdd(&out[(size_t)dst * OC + lane],      acc0);
    atomicAdd(&out[(size_t)dst * OC + 32 + lane], acc1);
}

// ---------------- launch ----------------------------------------
extern "C" void kernel_launch(void* const* d_in, const int* in_sizes, int n_in,
                              void* d_out, int out_size) {
    const float* feature    = (const float*)d_in[0];
    const void*  edge_index = d_in[1];
    const float* lin_w      = (const float*)d_in[2];
    const float* att_src    = (const float*)d_in[3];
    const float* att_dst    = (const float*)d_in[4];
    const float* bias       = (const float*)d_in[5];
    float*       out        = (float*)d_out;

    detect_kernel<<<1, 256>>>((const int*)edge_index);

    init_kernel<<<(NN * OC + 255) / 256, 256>>>(out, bias);

    dim3 ggrid((NN + 63) / 64, HC / 64);
    gemm_kernel<<<ggrid, 256>>>(feature, lin_w);

    logits_kernel<<<(NN * NH + 255) / 256, 256>>>(att_src, att_dst);

    edge_kernel<<<(NET + 255) / 256, 256>>>(edge_index);

    scatter_kernel<<<((size_t)NET * 32 + 255) / 256, 256>>>(edge_index, out);
}

// round 2
// speedup vs baseline: 1.1644x; 1.1644x over previous
#include <cuda_runtime.h>
#include <stdint.h>

// Problem constants (fixed by reference)
#define NN   50000      // nodes
#define NE   800000     // edges (before self loops)
#define NET  850000     // edges + self loops
#define ICH  128        // in channels
#define HC   256        // heads * out = 4*64
#define OC   64         // out channels
#define NH   4          // heads

// ---------------- device scratch (allocation-free) ----------------
__device__ __align__(16) float g_x[(size_t)NN * HC];   // projected features [N, H*C]
__device__ __align__(16) float g_asrc[NN * NH];        // per-node src logits
__device__ __align__(16) float g_adst[NN * NH];        // per-node dst logits
__device__ __align__(16) float g_ex[(size_t)NET * NH]; // per-edge exp(alpha)
__device__ __align__(16) float g_denom[NN * NH];       // softmax denominators
__device__ int   g_is64;                               // edge_index dtype flag

// ---------------- dtype detection -------------------------------
// If edge_index is int64 (little-endian, values in [0, 50000)), every odd
// 32-bit word of the first 2048 entries is zero. If int32, those words are
// random node ids -> practically impossible to all be zero.
__global__ void detect_kernel(const int* __restrict__ idx32) {
    __shared__ int bad;
    if (threadIdx.x == 0) bad = 0;
    __syncthreads();
    for (int i = threadIdx.x; i < 2048; i += blockDim.x) {
        if (idx32[2 * i + 1] != 0) bad = 1;
    }
    __syncthreads();
    if (threadIdx.x == 0) g_is64 = bad ? 0 : 1;
}

// ---------------- init: out = bias (broadcast), denom = 0 --------
__global__ void init_kernel(float* __restrict__ out, const float* __restrict__ bias) {
    int i = blockIdx.x * blockDim.x + threadIdx.x;
    if (i < NN * OC) out[i] = bias[i & (OC - 1)];
    if (i < NN * NH) g_denom[i] = 0.0f;
}

// ---------------- GEMM + fused logits epilogue -------------------
// g_x = feature[N,128] @ lin_w[128,256]; BM=BN=64, BK=16, 256 thr, 4x4/thread.
// BN == OC, so blockIdx.y IS the head index: the epilogue reduces
// acc[i][j]*att[h][c] across the 16 lanes owning one row to produce the
// per-(node,head) attention logits with no extra global traffic.
__global__ void __launch_bounds__(256) gemm_kernel(const float* __restrict__ A,
                                                   const float* __restrict__ B,
                                                   const float* __restrict__ att_s,
                                                   const float* __restrict__ att_d) {
    __shared__ float As[16][64];   // k-major A tile
    __shared__ float Bs[16][64];
    const int bm = blockIdx.x * 64;
    const int h  = blockIdx.y;      // head (bn = h*64)
    const int bn = h * 64;
    const int t  = threadIdx.x;
    const int ty = t >> 4;          // 0..15 -> M sub-tile
    const int tx = t & 15;          // 0..15 -> N sub-tile

    const int ar = t >> 2;          // A load: row 0..63
    const int ac = (t & 3) * 4;     // A load: k 0..12 step 4
    const int br = t >> 4;          // B load: k 0..15
    const int bc = (t & 15) * 4;    // B load: col 0..60 step 4

    float acc[4][4] = {};

    for (int k0 = 0; k0 < ICH; k0 += 16) {
        float4 av;
        if (bm + ar < NN)
            av = *(const float4*)&A[(size_t)(bm + ar) * ICH + k0 + ac];
        else
            av = make_float4(0.f, 0.f, 0.f, 0.f);
        As[ac + 0][ar] = av.x;
        As[ac + 1][ar] = av.y;
        As[ac + 2][ar] = av.z;
        As[ac + 3][ar] = av.w;

        *(float4*)&Bs[br][bc] = *(const float4*)&B[(size_t)(k0 + br) * HC + bn + bc];
        __syncthreads();

#pragma unroll
        for (int k = 0; k < 16; k++) {
            float a0 = As[k][ty * 4 + 0];
            float a1 = As[k][ty * 4 + 1];
            float a2 = As[k][ty * 4 + 2];
            float a3 = As[k][ty * 4 + 3];
            float b0 = Bs[k][tx * 4 + 0];
            float b1 = Bs[k][tx * 4 + 1];
            float b2 = Bs[k][tx * 4 + 2];
            float b3 = Bs[k][tx * 4 + 3];
            acc[0][0] += a0 * b0; acc[0][1] += a0 * b1; acc[0][2] += a0 * b2; acc[0][3] += a0 * b3;
            acc[1][0] += a1 * b0; acc[1][1] += a1 * b1; acc[1][2] += a1 * b2; acc[1][3] += a1 * b3;
            acc[2][0] += a2 * b0; acc[2][1] += a2 * b1; acc[2][2] += a2 * b2; acc[2][3] += a2 * b3;
            acc[3][0] += a3 * b0; acc[3][1] += a3 * b1; acc[3][2] += a3 * b2; acc[3][3] += a3 * b3;
        }
        __syncthreads();
    }

    // store x tile
#pragma unroll
    for (int i = 0; i < 4; i++) {
        int row = bm + ty * 4 + i;
        if (row < NN) {
            float4 v = make_float4(acc[i][0], acc[i][1], acc[i][2], acc[i][3]);
            *(float4*)&g_x[(size_t)row * HC + bn + tx * 4] = v;
        }
    }

    // fused logits: s(row,h) = sum_c acc * att_s[h][c]; 16-lane reduction.
    float4 avs = *(const float4*)&att_s[h * OC + tx * 4];
    float4 avd = *(const float4*)&att_d[h * OC + tx * 4];
#pragma unroll
    for (int i = 0; i < 4; i++) {
        float s = acc[i][0] * avs.x + acc[i][1] * avs.y + acc[i][2] * avs.z + acc[i][3] * avs.w;
        float d = acc[i][0] * avd.x + acc[i][1] * avd.y + acc[i][2] * avd.z + acc[i][3] * avd.w;
#pragma unroll
        for (int off = 8; off >= 1; off >>= 1) {
            s += __shfl_xor_sync(0xffffffffu, s, off);
            d += __shfl_xor_sync(0xffffffffu, d, off);
        }
        int row = bm + ty * 4 + i;
        if (tx == 0 && row < NN) {
            g_asrc[row * NH + h] = s;
            g_adst[row * NH + h] = d;
        }
    }
}

// ---------------- edge pass: exp(leaky_relu(logit)), denom accum --
__global__ void edge_kernel(const void* __restrict__ idx) {
    int e = blockIdx.x * blockDim.x + threadIdx.x;
    if (e >= NET) return;
    int src, dst;
    if (e < NE) {
        if (g_is64) {
            const long long* p = (const long long*)idx;
            src = (int)p[e];
            dst = (int)p[NE + e];
        } else {
            const int* p = (const int*)idx;
            src = p[e];
            dst = p[NE + e];
        }
    } else {
        src = dst = e - NE;
    }
    float4 as = *(const float4*)&g_asrc[src * NH];
    float4 ad = *(const float4*)&g_adst[dst * NH];
    float al[4] = { as.x + ad.x, as.y + ad.y, as.z + ad.z, as.w + ad.w };
    float ex[4];
#pragma unroll
    for (int h = 0; h < 4; h++) {
        float v = al[h];
        v = v > 0.f ? v : 0.2f * v;        // leaky_relu, slope 0.2
        ex[h] = __expf(v);                  // no max-shift: |v| <= ~8, safe in fp32
        atomicAdd(&g_denom[dst * NH + h], ex[h]);
    }
    *(float4*)&g_ex[(size_t)e * NH] = make_float4(ex[0], ex[1], ex[2], ex[3]);
}

// ---------------- scatter: out[dst,c] += sum_h w_h * x[src,h,c] / 4 ----
// one warp per edge. Lanes 0-15 accumulate heads {0,1}, lanes 16-31 heads
// {2,3}, each owning channel quad q=lane&15. One shfl_xor(16) combine, then
// 16 float4 REDs per edge (4x fewer RED lanes than scalar).
__global__ void __launch_bounds__(256) scatter_kernel(const void* __restrict__ idx,
                                                      float* __restrict__ out) {
    int gtid = blockIdx.x * blockDim.x + threadIdx.x;
    int e    = gtid >> 5;
    int lane = threadIdx.x & 31;
    if (e >= NET) return;

    int src, dst;
    if (e < NE) {
        if (g_is64) {
            const long long* p = (const long long*)idx;
            src = (int)p[e];
            dst = (int)p[NE + e];
        } else {
            const int* p = (const int*)idx;
            src = p[e];
            dst = p[NE + e];
        }
    } else {
        src = dst = e - NE;
    }

    float w = 0.f;
    if (lane < 4)
        w = g_ex[(size_t)e * NH + lane] / g_denom[dst * NH + lane] * 0.25f;
    float w0 = __shfl_sync(0xffffffffu, w, 0);
    float w1 = __shfl_sync(0xffffffffu, w, 1);
    float w2 = __shfl_sync(0xffffffffu, w, 2);
    float w3 = __shfl_sync(0xffffffffu, w, 3);

    const int q  = lane & 15;    // channel quad
    const int hh = lane >> 4;    // 0 -> heads 0,1 ; 1 -> heads 2,3
    const float wa = hh ? w2 : w0;
    const float wb = hh ? w3 : w1;

    const float4* xr = (const float4*)&g_x[(size_t)src * HC];
    float4 xa = xr[(2 * hh) * 16 + q];
    float4 xb = xr[(2 * hh + 1) * 16 + q];

    float4 acc;
    acc.x = wa * xa.x + wb * xb.x;
    acc.y = wa * xa.y + wb * xb.y;
    acc.z = wa * xa.z + wb * xb.z;
    acc.w = wa * xa.w + wb * xb.w;

    acc.x += __shfl_xor_sync(0xffffffffu, acc.x, 16);
    acc.y += __shfl_xor_sync(0xffffffffu, acc.y, 16);
    acc.z += __shfl_xor_sync(0xffffffffu, acc.z, 16);
    acc.w += __shfl_xor_sync(0xffffffffu, acc.w, 16);

    if (lane < 16)
        atomicAdd((float4*)&out[(size_t)dst * OC + 4 * q], acc);
}

// ---------------- launch ----------------------------------------
extern "C" void kernel_launch(void* const* d_in, const int* in_sizes, int n_in,
                              void* d_out, int out_size) {
    const float* feature    = (const float*)d_in[0];
    const void*  edge_index = d_in[1];
    const float* lin_w      = (const float*)d_in[2];
    const float* att_src    = (const float*)d_in[3];
    const float* att_dst    = (const float*)d_in[4];
    const float* bias       = (const float*)d_in[5];
    float*       out        = (float*)d_out;

    detect_kernel<<<1, 256>>>((const int*)edge_index);

    init_kernel<<<(NN * OC + 255) / 256, 256>>>(out, bias);

    dim3 ggrid((NN + 63) / 64, HC / 64);
    gemm_kernel<<<ggrid, 256>>>(feature, lin_w, att_src, att_dst);

    edge_kernel<<<(NET + 255) / 256, 256>>>(edge_index);

    scatter_kernel<<<((size_t)NET * 32 + 255) / 256, 256>>>(edge_index, out);
}

// round 3
// speedup vs baseline: 1.2410x; 1.0658x over previous
#include <cuda_runtime.h>
#include <stdint.h>

// Problem constants (fixed by reference)
#define NN   50000      // nodes
#define NE   800000     // edges (before self loops)
#define NET  850000     // edges + self loops
#define ICH  128        // in channels
#define HC   256        // heads * out = 4*64
#define OC   64         // out channels
#define NH   4          // heads

// ---------------- device scratch (allocation-free) ----------------
__device__ __align__(16) float g_x[(size_t)NN * HC];   // projected features [N, H*C]
__device__ __align__(16) float g_asrc[NN * NH];        // per-node src logits
__device__ __align__(16) float g_adst[NN * NH];        // per-node dst logits
__device__ __align__(16) float g_ex[(size_t)NET * NH]; // per-edge exp(alpha)
__device__ __align__(16) float g_denom[NN * NH];       // softmax denominators
__device__ int   g_is64;                               // edge_index dtype flag

// ---------------- helpers ----------------------------------------
__device__ __forceinline__ uint32_t f2tf32(float f) {
    uint32_t u;
    asm("cvt.rna.tf32.f32 %0, %1;" : "=r"(u) : "f"(f));
    return u;
}

__device__ __forceinline__ void mma_tf32(float c[4],
                                         uint32_t a0, uint32_t a1, uint32_t a2, uint32_t a3,
                                         uint32_t b0, uint32_t b1) {
    asm volatile(
        "mma.sync.aligned.m16n8k8.row.col.f32.tf32.tf32.f32 "
        "{%0,%1,%2,%3}, {%4,%5,%6,%7}, {%8,%9}, {%0,%1,%2,%3};"
        : "+f"(c[0]), "+f"(c[1]), "+f"(c[2]), "+f"(c[3])
        : "r"(a0), "r"(a1), "r"(a2), "r"(a3), "r"(b0), "r"(b1));
}

// ---------------- dtype detection -------------------------------
// If edge_index is int64 (little-endian, values in [0, 50000)), every odd
// 32-bit word of the first 2048 entries is zero. If int32, those words are
// random node ids -> practically impossible to all be zero.
__global__ void detect_kernel(const int* __restrict__ idx32) {
    __shared__ int bad;
    if (threadIdx.x == 0) bad = 0;
    __syncthreads();
    for (int i = threadIdx.x; i < 2048; i += blockDim.x) {
        if (idx32[2 * i + 1] != 0) bad = 1;
    }
    __syncthreads();
    if (threadIdx.x == 0) g_is64 = bad ? 0 : 1;
}

// ---------------- init: out = bias (broadcast), denom = 0 --------
__global__ void init_kernel(float* __restrict__ out, const float* __restrict__ bias) {
    int i = blockIdx.x * blockDim.x + threadIdx.x;
    if (i < NN * OC) out[i] = bias[i & (OC - 1)];
    if (i < NN * NH) g_denom[i] = 0.0f;
}

// ---------------- tf32 tensor-core GEMM + fused logits -----------
// g_x = feature[N,128] @ lin_w[128,256].
// Block: 128(M) x 64(N=one head), 8 warps in 4(M) x 2(N); warp tile 32x32
// via m16n8k8 tf32 mma (2 m-frags x 4 n-frags). A/B fragments loaded
// directly from global (L1-resident; no smem staging).
// Epilogue reduces acc * att over the 64 head channels into per-(node,head)
// logits: quad shuffle + cross-warp smem atomics.
__global__ void __launch_bounds__(256) gemm_kernel(const float* __restrict__ A,
                                                   const float* __restrict__ B,
                                                   const float* __restrict__ att_s,
                                                   const float* __restrict__ att_d) {
    const int bm   = blockIdx.x * 128;
    const int h    = blockIdx.y;       // head
    const int bn   = h * 64;
    const int wid  = threadIdx.x >> 5;
    const int lane = threadIdx.x & 31;
    const int wm   = wid & 3;          // warp row block (32 rows)
    const int wn   = wid >> 2;         // warp col block (32 cols)
    const int gid  = lane >> 2;        // 0..7
    const int tig  = lane & 3;         // 0..3

    const int colbase = bn + wn * 32;        // + nt*8 + gid
    const int r0      = bm + wm * 32 + gid;  // + mt*16 (+8)

    float acc[2][4][4];
#pragma unroll
    for (int mt = 0; mt < 2; mt++)
#pragma unroll
        for (int nt = 0; nt < 4; nt++)
#pragma unroll
            for (int c = 0; c < 4; c++) acc[mt][nt][c] = 0.f;

#pragma unroll 2
    for (int kb = 0; kb < ICH; kb += 8) {
        uint32_t bf[4][2];
#pragma unroll
        for (int nt = 0; nt < 4; nt++) {
            int col = colbase + nt * 8 + gid;
            bf[nt][0] = f2tf32(B[(size_t)(kb + tig) * HC + col]);
            bf[nt][1] = f2tf32(B[(size_t)(kb + tig + 4) * HC + col]);
        }
#pragma unroll
        for (int mt = 0; mt < 2; mt++) {
            int ra = r0 + mt * 16;
            int rb = ra + 8;
            bool ga = ra < NN, gb = rb < NN;
            uint32_t a0 = ga ? f2tf32(A[(size_t)ra * ICH + kb + tig])     : 0u;
            uint32_t a1 = gb ? f2tf32(A[(size_t)rb * ICH + kb + tig])     : 0u;
            uint32_t a2 = ga ? f2tf32(A[(size_t)ra * ICH + kb + tig + 4]) : 0u;
            uint32_t a3 = gb ? f2tf32(A[(size_t)rb * ICH + kb + tig + 4]) : 0u;
#pragma unroll
            for (int nt = 0; nt < 4; nt++)
                mma_tf32(acc[mt][nt], a0, a1, a2, a3, bf[nt][0], bf[nt][1]);
        }
    }

    // ---- store x + fused logits ----
    __shared__ float sS[128], sD[128];
    if (threadIdx.x < 128) { sS[threadIdx.x] = 0.f; sD[threadIdx.x] = 0.f; }
    __syncthreads();

#pragma unroll
    for (int mt = 0; mt < 2; mt++) {
        int ra = r0 + mt * 16;
        int rb = ra + 8;
        float s0 = 0.f, d0 = 0.f, s1 = 0.f, d1 = 0.f;
#pragma unroll
        for (int nt = 0; nt < 4; nt++) {
            int col = colbase + nt * 8 + 2 * tig;      // global col
            float2 v0 = make_float2(acc[mt][nt][0], acc[mt][nt][1]);
            float2 v1 = make_float2(acc[mt][nt][2], acc[mt][nt][3]);
            if (ra < NN) *(float2*)&g_x[(size_t)ra * HC + col] = v0;
            if (rb < NN) *(float2*)&g_x[(size_t)rb * HC + col] = v1;
            float2 as = *(const float2*)&att_s[h * OC + (col - bn)];
            float2 ad = *(const float2*)&att_d[h * OC + (col - bn)];
            s0 += v0.x * as.x + v0.y * as.y;
            d0 += v0.x * ad.x + v0.y * ad.y;
            s1 += v1.x * as.x + v1.y * as.y;
            d1 += v1.x * ad.x + v1.y * ad.y;
        }
#pragma unroll
        for (int off = 1; off <= 2; off <<= 1) {
            s0 += __shfl_xor_sync(0xffffffffu, s0, off);
            d0 += __shfl_xor_sync(0xffffffffu, d0, off);
            s1 += __shfl_xor_sync(0xffffffffu, s1, off);
            d1 += __shfl_xor_sync(0xffffffffu, d1, off);
        }
        if (tig == 0) {
            int rl = wm * 32 + mt * 16 + gid;
            atomicAdd(&sS[rl], s0);     atomicAdd(&sD[rl], d0);
            atomicAdd(&sS[rl + 8], s1); atomicAdd(&sD[rl + 8], d1);
        }
    }
    __syncthreads();
    if (threadIdx.x < 128) {
        int row = bm + threadIdx.x;
        if (row < NN) {
            g_asrc[row * NH + h] = sS[threadIdx.x];
            g_adst[row * NH + h] = sD[threadIdx.x];
        }
    }
}

// ---------------- edge pass: exp(leaky_relu(logit)), denom accum --
__global__ void edge_kernel(const void* __restrict__ idx) {
    int e = blockIdx.x * blockDim.x + threadIdx.x;
    if (e >= NET) return;
    int src, dst;
    if (e < NE) {
        if (g_is64) {
            const long long* p = (const long long*)idx;
            src = (int)p[e];
            dst = (int)p[NE + e];
        } else {
            const int* p = (const int*)idx;
            src = p[e];
            dst = p[NE + e];
        }
    } else {
        src = dst = e - NE;
    }
    float4 as = *(const float4*)&g_asrc[src * NH];
    float4 ad = *(const float4*)&g_adst[dst * NH];
    float al[4] = { as.x + ad.x, as.y + ad.y, as.z + ad.z, as.w + ad.w };
    float ex[4];
#pragma unroll
    for (int h = 0; h < 4; h++) {
        float v = al[h];
        v = v > 0.f ? v : 0.2f * v;        // leaky_relu, slope 0.2
        ex[h] = __expf(v);                  // no max-shift: |v| <= ~8, safe in fp32
        atomicAdd(&g_denom[dst * NH + h], ex[h]);
    }
    *(float4*)&g_ex[(size_t)e * NH] = make_float4(ex[0], ex[1], ex[2], ex[3]);
}

// ---------------- scatter: out[dst,c] += sum_h w_h * x[src,h,c] / 4 ----
// one warp per edge. Lanes 0-15 accumulate heads {0,1}, lanes 16-31 heads
// {2,3}, each owning channel quad q=lane&15. One shfl_xor(16) combine, then
// 16 float4 REDs per edge.
__global__ void __launch_bounds__(256) scatter_kernel(const void* __restrict__ idx,
                                                      float* __restrict__ out) {
    int gtid = blockIdx.x * blockDim.x + threadIdx.x;
    int e    = gtid >> 5;
    int lane = threadIdx.x & 31;
    if (e >= NET) return;

    int src, dst;
    if (e < NE) {
        if (g_is64) {
            const long long* p = (const long long*)idx;
            src = (int)p[e];
            dst = (int)p[NE + e];
        } else {
            const int* p = (const int*)idx;
            src = p[e];
            dst = p[NE + e];
        }
    } else {
        src = dst = e - NE;
    }

    float w = 0.f;
    if (lane < 4)
        w = g_ex[(size_t)e * NH + lane] / g_denom[dst * NH + lane] * 0.25f;
    float w0 = __shfl_sync(0xffffffffu, w, 0);
    float w1 = __shfl_sync(0xffffffffu, w, 1);
    float w2 = __shfl_sync(0xffffffffu, w, 2);
    float w3 = __shfl_sync(0xffffffffu, w, 3);

    const int q  = lane & 15;    // channel quad
    const int hh = lane >> 4;    // 0 -> heads 0,1 ; 1 -> heads 2,3
    const float wa = hh ? w2 : w0;
    const float wb = hh ? w3 : w1;

    const float4* xr = (const float4*)&g_x[(size_t)src * HC];
    float4 xa = xr[(2 * hh) * 16 + q];
    float4 xb = xr[(2 * hh + 1) * 16 + q];

    float4 acc;
    acc.x = wa * xa.x + wb * xb.x;
    acc.y = wa * xa.y + wb * xb.y;
    acc.z = wa * xa.z + wb * xb.z;
    acc.w = wa * xa.w + wb * xb.w;

    acc.x += __shfl_xor_sync(0xffffffffu, acc.x, 16);
    acc.y += __shfl_xor_sync(0xffffffffu, acc.y, 16);
    acc.z += __shfl_xor_sync(0xffffffffu, acc.z, 16);
    acc.w += __shfl_xor_sync(0xffffffffu, acc.w, 16);

    if (lane < 16)
        atomicAdd((float4*)&out[(size_t)dst * OC + 4 * q], acc);
}

// ---------------- launch ----------------------------------------
extern "C" void kernel_launch(void* const* d_in, const int* in_sizes, int n_in,
                              void* d_out, int out_size) {
    const float* feature    = (const float*)d_in[0];
    const void*  edge_index = d_in[1];
    const float* lin_w      = (const float*)d_in[2];
    const float* att_src    = (const float*)d_in[3];
    const float* att_dst    = (const float*)d_in[4];
    const float* bias       = (const float*)d_in[5];
    float*       out        = (float*)d_out;

    detect_kernel<<<1, 256>>>((const int*)edge_index);

    init_kernel<<<(NN * OC + 255) / 256, 256>>>(out, bias);

    dim3 ggrid((NN + 127) / 128, NH);
    gemm_kernel<<<ggrid, 256>>>(feature, lin_w, att_src, att_dst);

    edge_kernel<<<(NET + 255) / 256, 256>>>(edge_index);

    scatter_kernel<<<((size_t)NET * 32 + 255) / 256, 256>>>(edge_index, out);
}

// round 4
// speedup vs baseline: 1.4287x; 1.1513x over previous
#include <cuda_runtime.h>
#include <stdint.h>

// Problem constants (fixed by reference)
#define NN   50000      // nodes
#define NE   800000     // edges (before self loops)
#define NET  850000     // edges + self loops
#define ICH  128        // in channels
#define HC   256        // heads * out = 4*64
#define OC   64         // out channels
#define NH   4          // heads

#define SCAN_BLK 1024
#define NBLK     ((NN + SCAN_BLK - 1) / SCAN_BLK)   // 49
#define NPAD     (NBLK * SCAN_BLK)                  // 50176

// ---------------- device scratch (allocation-free) ----------------
__device__ __align__(16) float g_x[(size_t)NN * HC];   // projected features [N, H*C]
__device__ __align__(16) float g_asrc[NN * NH];        // per-node src logits
__device__ __align__(16) float g_adst[NN * NH];        // per-node dst logits
__device__ int   g_count[NPAD];                        // in-degree per dst
__device__ int   g_start[NPAD];                        // CSR row starts (excl scan)
__device__ int   g_cursor[NPAD];                       // fill cursors
__device__ int   g_csr[NET];                           // src ids grouped by dst
__device__ int   g_bsum[NBLK];                         // scan block sums
__device__ int   g_is64;                               // edge_index dtype flag

// ---------------- helpers ----------------------------------------
__device__ __forceinline__ uint32_t f2tf32(float f) {
    uint32_t u;
    asm("cvt.rna.tf32.f32 %0, %1;" : "=r"(u) : "f"(f));
    return u;
}

__device__ __forceinline__ void mma_tf32(float c[4],
                                         uint32_t a0, uint32_t a1, uint32_t a2, uint32_t a3,
                                         uint32_t b0, uint32_t b1) {
    asm volatile(
        "mma.sync.aligned.m16n8k8.row.col.f32.tf32.tf32.f32 "
        "{%0,%1,%2,%3}, {%4,%5,%6,%7}, {%8,%9}, {%0,%1,%2,%3};"
        : "+f"(c[0]), "+f"(c[1]), "+f"(c[2]), "+f"(c[3])
        : "r"(a0), "r"(a1), "r"(a2), "r"(a3), "r"(b0), "r"(b1));
}

__device__ __forceinline__ void load_edge(const void* idx, int e, int& src, int& dst) {
    if (e < NE) {
        if (g_is64) {
            const long long* p = (const long long*)idx;
            src = (int)p[e];
            dst = (int)p[NE + e];
        } else {
            const int* p = (const int*)idx;
            src = p[e];
            dst = p[NE + e];
        }
    } else {
        src = dst = e - NE;   // self loop
    }
}

// ---------------- dtype detection -------------------------------
// int64 little-endian node ids < 50000 => every odd 32-bit word zero.
__global__ void detect_kernel(const int* __restrict__ idx32) {
    __shared__ int bad;
    if (threadIdx.x == 0) bad = 0;
    __syncthreads();
    for (int i = threadIdx.x; i < 2048; i += blockDim.x) {
        if (idx32[2 * i + 1] != 0) bad = 1;
    }
    __syncthreads();
    if (threadIdx.x == 0) g_is64 = bad ? 0 : 1;
}

// ---------------- zero counters ----------------------------------
__global__ void zero_kernel() {
    int i = blockIdx.x * blockDim.x + threadIdx.x;
    if (i < NPAD) g_count[i] = 0;
}

// ---------------- histogram of in-degrees ------------------------
__global__ void hist_kernel(const void* __restrict__ idx) {
    int e = blockIdx.x * blockDim.x + threadIdx.x;
    if (e >= NET) return;
    int src, dst;
    load_edge(idx, e, src, dst);
    atomicAdd(&g_count[dst], 1);
}

// ---------------- scan pass 1: per-block inclusive scan ----------
__global__ void __launch_bounds__(SCAN_BLK) scan1_kernel() {
    __shared__ int sh[SCAN_BLK];
    int i = blockIdx.x * SCAN_BLK + threadIdx.x;
    int v = g_count[i];
    sh[threadIdx.x] = v;
    __syncthreads();
#pragma unroll
    for (int off = 1; off < SCAN_BLK; off <<= 1) {
        int t = (threadIdx.x >= off) ? sh[threadIdx.x - off] : 0;
        __syncthreads();
        sh[threadIdx.x] += t;
        __syncthreads();
    }
    g_start[i] = sh[threadIdx.x];           // inclusive scan within block
    if (threadIdx.x == SCAN_BLK - 1) g_bsum[blockIdx.x] = sh[threadIdx.x];
}

// ---------------- scan pass 2: exclusive scan of block sums ------
__global__ void scan2_kernel() {
    __shared__ int sh[64];
    int v = (threadIdx.x < NBLK) ? g_bsum[threadIdx.x] : 0;
    sh[threadIdx.x] = v;
    __syncthreads();
    for (int off = 1; off < 64; off <<= 1) {
        int t = (threadIdx.x >= off) ? sh[threadIdx.x - off] : 0;
        __syncthreads();
        sh[threadIdx.x] += t;
        __syncthreads();
    }
    if (threadIdx.x < NBLK)
        g_bsum[threadIdx.x] = sh[threadIdx.x] - v;   // exclusive
}

// ---------------- scan pass 3: exclusive starts + cursors --------
__global__ void scan3_kernel() {
    int i = blockIdx.x * blockDim.x + threadIdx.x;
    if (i >= NPAD) return;
    int s = g_start[i] - g_count[i] + g_bsum[i / SCAN_BLK];
    g_start[i]  = s;
    g_cursor[i] = s;
}

// ---------------- fill CSR ---------------------------------------
__global__ void fill_kernel(const void* __restrict__ idx) {
    int e = blockIdx.x * blockDim.x + threadIdx.x;
    if (e >= NET) return;
    int src, dst;
    load_edge(idx, e, src, dst);
    int pos = atomicAdd(&g_cursor[dst], 1);
    g_csr[pos] = src;
}

// ---------------- tf32 tensor-core GEMM + fused logits -----------
// g_x = feature[N,128] @ lin_w[128,256]; block 128x64 (blockIdx.y = head),
// 8 warps 4x2, warp tile 32x32 via m16n8k8 tf32 mma, operands straight
// from global (L1-resident). Epilogue: per-(node,head) attention logits.
__global__ void __launch_bounds__(256) gemm_kernel(const float* __restrict__ A,
                                                   const float* __restrict__ B,
                                                   const float* __restrict__ att_s,
                                                   const float* __restrict__ att_d) {
    const int bm   = blockIdx.x * 128;
    const int h    = blockIdx.y;       // head
    const int bn   = h * 64;
    const int wid  = threadIdx.x >> 5;
    const int lane = threadIdx.x & 31;
    const int wm   = wid & 3;          // warp row block (32 rows)
    const int wn   = wid >> 2;         // warp col block (32 cols)
    const int gid  = lane >> 2;        // 0..7
    const int tig  = lane & 3;         // 0..3

    const int colbase = bn + wn * 32;
    const int r0      = bm + wm * 32 + gid;

    float acc[2][4][4];
#pragma unroll
    for (int mt = 0; mt < 2; mt++)
#pragma unroll
        for (int nt = 0; nt < 4; nt++)
#pragma unroll
            for (int c = 0; c < 4; c++) acc[mt][nt][c] = 0.f;

#pragma unroll 2
    for (int kb = 0; kb < ICH; kb += 8) {
        uint32_t bf[4][2];
#pragma unroll
        for (int nt = 0; nt < 4; nt++) {
            int col = colbase + nt * 8 + gid;
            bf[nt][0] = f2tf32(B[(size_t)(kb + tig) * HC + col]);
            bf[nt][1] = f2tf32(B[(size_t)(kb + tig + 4) * HC + col]);
        }
#pragma unroll
        for (int mt = 0; mt < 2; mt++) {
            int ra = r0 + mt * 16;
            int rb = ra + 8;
            bool ga = ra < NN, gb = rb < NN;
            uint32_t a0 = ga ? f2tf32(A[(size_t)ra * ICH + kb + tig])     : 0u;
            uint32_t a1 = gb ? f2tf32(A[(size_t)rb * ICH + kb + tig])     : 0u;
            uint32_t a2 = ga ? f2tf32(A[(size_t)ra * ICH + kb + tig + 4]) : 0u;
            uint32_t a3 = gb ? f2tf32(A[(size_t)rb * ICH + kb + tig + 4]) : 0u;
#pragma unroll
            for (int nt = 0; nt < 4; nt++)
                mma_tf32(acc[mt][nt], a0, a1, a2, a3, bf[nt][0], bf[nt][1]);
        }
    }

    __shared__ float sS[128], sD[128];
    if (threadIdx.x < 128) { sS[threadIdx.x] = 0.f; sD[threadIdx.x] = 0.f; }
    __syncthreads();

#pragma unroll
    for (int mt = 0; mt < 2; mt++) {
        int ra = r0 + mt * 16;
        int rb = ra + 8;
        float s0 = 0.f, d0 = 0.f, s1 = 0.f, d1 = 0.f;
#pragma unroll
        for (int nt = 0; nt < 4; nt++) {
            int col = colbase + nt * 8 + 2 * tig;
            float2 v0 = make_float2(acc[mt][nt][0], acc[mt][nt][1]);
            float2 v1 = make_float2(acc[mt][nt][2], acc[mt][nt][3]);
            if (ra < NN) *(float2*)&g_x[(size_t)ra * HC + col] = v0;
            if (rb < NN) *(float2*)&g_x[(size_t)rb * HC + col] = v1;
            float2 as = *(const float2*)&att_s[h * OC + (col - bn)];
            float2 ad = *(const float2*)&att_d[h * OC + (col - bn)];
            s0 += v0.x * as.x + v0.y * as.y;
            d0 += v0.x * ad.x + v0.y * ad.y;
            s1 += v1.x * as.x + v1.y * as.y;
            d1 += v1.x * ad.x + v1.y * ad.y;
        }
#pragma unroll
        for (int off = 1; off <= 2; off <<= 1) {
            s0 += __shfl_xor_sync(0xffffffffu, s0, off);
            d0 += __shfl_xor_sync(0xffffffffu, d0, off);
            s1 += __shfl_xor_sync(0xffffffffu, s1, off);
            d1 += __shfl_xor_sync(0xffffffffu, d1, off);
        }
        if (tig == 0) {
            int rl = wm * 32 + mt * 16 + gid;
            atomicAdd(&sS[rl], s0);     atomicAdd(&sD[rl], d0);
            atomicAdd(&sS[rl + 8], s1); atomicAdd(&sD[rl + 8], d1);
        }
    }
    __syncthreads();
    if (threadIdx.x < 128) {
        int row = bm + threadIdx.x;
        if (row < NN) {
            g_asrc[row * NH + h] = sS[threadIdx.x];
            g_adst[row * NH + h] = sD[threadIdx.x];
        }
    }
}

// ---------------- fused attention gather: warp per dst node ------
// For each dst: single pass over its in-edges, accumulating
//   den_h  += ex_h,     acc_{h,c} += ex_h * x[src,h,c]
// then out[dst,c] = 0.25 * sum_h acc_{h,c}/den_h + bias[c].
// Lane owns channels {lane, lane+32} across all 4 heads (8 accumulators).
// Per-edge scalar loads are warp-uniform (broadcast); x gathers are 8
// coalesced 128B warp loads. Next edge's src/a_src prefetched for MLP.
__global__ void __launch_bounds__(256) gather_kernel(float* __restrict__ out,
                                                     const float* __restrict__ bias) {
    int dst  = (blockIdx.x * blockDim.x + threadIdx.x) >> 5;
    int lane = threadIdx.x & 31;
    if (dst >= NN) return;

    const int beg = g_start[dst];
    const int cnt = g_count[dst];
    const float4 ad = *(const float4*)&g_adst[dst * NH];

    float acc0[4] = {0.f, 0.f, 0.f, 0.f};   // channels [h*64 + lane]
    float acc1[4] = {0.f, 0.f, 0.f, 0.f};   // channels [h*64 + 32 + lane]
    float den[4]  = {0.f, 0.f, 0.f, 0.f};

    int   src_n = g_csr[beg];
    float4 as_n = *(const float4*)&g_asrc[src_n * NH];

    for (int i = 0; i < cnt; i++) {
        int    src = src_n;
        float4 as  = as_n;
        if (i + 1 < cnt) {
            src_n = g_csr[beg + i + 1];
            as_n  = *(const float4*)&g_asrc[src_n * NH];
        }
        float al[4] = { as.x + ad.x, as.y + ad.y, as.z + ad.z, as.w + ad.w };
        float ex[4];
#pragma unroll
        for (int h = 0; h < 4; h++) {
            float v = al[h];
            v = v > 0.f ? v : 0.2f * v;     // leaky_relu slope 0.2
            ex[h] = __expf(v);              // no max-shift needed (|v| small)
            den[h] += ex[h];
        }
        const float* xr = &g_x[(size_t)src * HC];
#pragma unroll
        for (int h = 0; h < 4; h++) {
            acc0[h] += ex[h] * xr[h * 64 + lane];
            acc1[h] += ex[h] * xr[h * 64 + 32 + lane];
        }
    }

    float o0 = 0.f, o1 = 0.f;
#pragma unroll
    for (int h = 0; h < 4; h++) {
        float r = 1.0f / den[h];
        o0 += acc0[h] * r;
        o1 += acc1[h] * r;
    }
    out[(size_t)dst * OC + lane]      = 0.25f * o0 + bias[lane];
    out[(size_t)dst * OC + 32 + lane] = 0.25f * o1 + bias[32 + lane];
}

// ---------------- launch ----------------------------------------
extern "C" void kernel_launch(void* const* d_in, const int* in_sizes, int n_in,
                              void* d_out, int out_size) {
    const float* feature    = (const float*)d_in[0];
    const void*  edge_index = d_in[1];
    const float* lin_w      = (const float*)d_in[2];
    const float* att_src    = (const float*)d_in[3];
    const float* att_dst    = (const float*)d_in[4];
    const float* bias       = (const float*)d_in[5];
    float*       out        = (float*)d_out;

    detect_kernel<<<1, 256>>>((const int*)edge_index);
    zero_kernel<<<(NPAD + 255) / 256, 256>>>();

    dim3 ggrid((NN + 127) / 128, NH);
    gemm_kernel<<<ggrid, 256>>>(feature, lin_w, att_src, att_dst);

    hist_kernel<<<(NET + 255) / 256, 256>>>(edge_index);
    scan1_kernel<<<NBLK, SCAN_BLK>>>();
    scan2_kernel<<<1, 64>>>();
    scan3_kernel<<<(NPAD + 255) / 256, 256>>>();
    fill_kernel<<<(NET + 255) / 256, 256>>>(edge_index);

    gather_kernel<<<(NN * 32 + 255) / 256, 256>>>(out, bias);
}

// round 5
// speedup vs baseline: 1.4531x; 1.0171x over previous
#include <cuda_runtime.h>
#include <stdint.h>

// Problem constants (fixed by reference)
#define NN   50000      // nodes
#define NE   800000     // edges (before self loops)
#define NET  850000     // edges + self loops
#define ICH  128        // in channels
#define HC   256        // heads * out = 4*64
#define OC   64         // out channels
#define NH   4          // heads

#define SCAN_BLK 1024
#define NBLK     ((NN + SCAN_BLK - 1) / SCAN_BLK)   // 49
#define NPAD     (NBLK * SCAN_BLK)                  // 50176

// ---------------- device scratch (allocation-free) ----------------
__device__ __align__(16) float g_x[(size_t)NN * HC];   // projected features [N, H*C]
__device__ __align__(16) float g_asrc[NN * NH];        // per-node src logits
__device__ __align__(16) float g_adst[NN * NH];        // per-node dst logits
__device__ int   g_count[NPAD];                        // in-degree per dst
__device__ int   g_start[NPAD];                        // CSR row starts (excl scan)
__device__ int   g_cursor[NPAD];                       // fill cursors
__device__ int   g_csr[NET];                           // src ids grouped by dst
__device__ int   g_bsum[NBLK];                         // scan block sums
__device__ int   g_is64;                               // edge_index dtype flag

// ---------------- helpers ----------------------------------------
__device__ __forceinline__ uint32_t f2tf32(float f) {
    uint32_t u;
    asm("cvt.rna.tf32.f32 %0, %1;" : "=r"(u) : "f"(f));
    return u;
}

__device__ __forceinline__ void mma_tf32(float c[4],
                                         uint32_t a0, uint32_t a1, uint32_t a2, uint32_t a3,
                                         uint32_t b0, uint32_t b1) {
    asm volatile(
        "mma.sync.aligned.m16n8k8.row.col.f32.tf32.tf32.f32 "
        "{%0,%1,%2,%3}, {%4,%5,%6,%7}, {%8,%9}, {%0,%1,%2,%3};"
        : "+f"(c[0]), "+f"(c[1]), "+f"(c[2]), "+f"(c[3])
        : "r"(a0), "r"(a1), "r"(a2), "r"(a3), "r"(b0), "r"(b1));
}

__device__ __forceinline__ void load_edge(const void* idx, int e, int& src, int& dst) {
    if (e < NE) {
        if (g_is64) {
            const long long* p = (const long long*)idx;
            src = (int)p[e];
            dst = (int)p[NE + e];
        } else {
            const int* p = (const int*)idx;
            src = p[e];
            dst = p[NE + e];
        }
    } else {
        src = dst = e - NE;   // self loop
    }
}

__device__ __forceinline__ float comp4(float4 v, int h) {
    return h == 0 ? v.x : h == 1 ? v.y : h == 2 ? v.z : v.w;
}

// ---------------- dtype detection -------------------------------
// int64 little-endian node ids < 50000 => every odd 32-bit word zero.
__global__ void detect_kernel(const int* __restrict__ idx32) {
    __shared__ int bad;
    if (threadIdx.x == 0) bad = 0;
    __syncthreads();
    for (int i = threadIdx.x; i < 2048; i += blockDim.x) {
        if (idx32[2 * i + 1] != 0) bad = 1;
    }
    __syncthreads();
    if (threadIdx.x == 0) g_is64 = bad ? 0 : 1;
}

// ---------------- zero counters ----------------------------------
__global__ void zero_kernel() {
    int i = blockIdx.x * blockDim.x + threadIdx.x;
    if (i < NPAD) g_count[i] = 0;
}

// ---------------- histogram of in-degrees ------------------------
__global__ void hist_kernel(const void* __restrict__ idx) {
    int e = blockIdx.x * blockDim.x + threadIdx.x;
    if (e >= NET) return;
    int src, dst;
    load_edge(idx, e, src, dst);
    atomicAdd(&g_count[dst], 1);
}

// ---------------- scan pass 1: per-block inclusive scan ----------
__global__ void __launch_bounds__(SCAN_BLK) scan1_kernel() {
    __shared__ int sh[SCAN_BLK];
    int i = blockIdx.x * SCAN_BLK + threadIdx.x;
    int v = g_count[i];
    sh[threadIdx.x] = v;
    __syncthreads();
#pragma unroll
    for (int off = 1; off < SCAN_BLK; off <<= 1) {
        int t = (threadIdx.x >= off) ? sh[threadIdx.x - off] : 0;
        __syncthreads();
        sh[threadIdx.x] += t;
        __syncthreads();
    }
    g_start[i] = sh[threadIdx.x];           // inclusive scan within block
    if (threadIdx.x == SCAN_BLK - 1) g_bsum[blockIdx.x] = sh[threadIdx.x];
}

// ---------------- scan pass 2: exclusive scan of block sums ------
__global__ void scan2_kernel() {
    __shared__ int sh[64];
    int v = (threadIdx.x < NBLK) ? g_bsum[threadIdx.x] : 0;
    sh[threadIdx.x] = v;
    __syncthreads();
    for (int off = 1; off < 64; off <<= 1) {
        int t = (threadIdx.x >= off) ? sh[threadIdx.x - off] : 0;
        __syncthreads();
        sh[threadIdx.x] += t;
        __syncthreads();
    }
    if (threadIdx.x < NBLK)
        g_bsum[threadIdx.x] = sh[threadIdx.x] - v;   // exclusive
}

// ---------------- scan pass 3: exclusive starts + cursors --------
__global__ void scan3_kernel() {
    int i = blockIdx.x * blockDim.x + threadIdx.x;
    if (i >= NPAD) return;
    int s = g_start[i] - g_count[i] + g_bsum[i / SCAN_BLK];
    g_start[i]  = s;
    g_cursor[i] = s;
}

// ---------------- fill CSR ---------------------------------------
__global__ void fill_kernel(const void* __restrict__ idx) {
    int e = blockIdx.x * blockDim.x + threadIdx.x;
    if (e >= NET) return;
    int src, dst;
    load_edge(idx, e, src, dst);
    int pos = atomicAdd(&g_cursor[dst], 1);
    g_csr[pos] = src;
}

// ---------------- tf32 tensor-core GEMM + fused logits -----------
// g_x = feature[N,128] @ lin_w[128,256]; block 128x64 (blockIdx.y = head),
// 8 warps 4x2, warp tile 32x32 via m16n8k8 tf32 mma, operands straight
// from global (L1-resident). Epilogue: per-(node,head) attention logits.
__global__ void __launch_bounds__(256) gemm_kernel(const float* __restrict__ A,
                                                   const float* __restrict__ B,
                                                   const float* __restrict__ att_s,
                                                   const float* __restrict__ att_d) {
    const int bm   = blockIdx.x * 128;
    const int h    = blockIdx.y;       // head
    const int bn   = h * 64;
    const int wid  = threadIdx.x >> 5;
    const int lane = threadIdx.x & 31;
    const int wm   = wid & 3;          // warp row block (32 rows)
    const int wn   = wid >> 2;         // warp col block (32 cols)
    const int gid  = lane >> 2;        // 0..7
    const int tig  = lane & 3;         // 0..3

    const int colbase = bn + wn * 32;
    const int r0      = bm + wm * 32 + gid;

    float acc[2][4][4];
#pragma unroll
    for (int mt = 0; mt < 2; mt++)
#pragma unroll
        for (int nt = 0; nt < 4; nt++)
#pragma unroll
            for (int c = 0; c < 4; c++) acc[mt][nt][c] = 0.f;

#pragma unroll 2
    for (int kb = 0; kb < ICH; kb += 8) {
        uint32_t bf[4][2];
#pragma unroll
        for (int nt = 0; nt < 4; nt++) {
            int col = colbase + nt * 8 + gid;
            bf[nt][0] = f2tf32(B[(size_t)(kb + tig) * HC + col]);
            bf[nt][1] = f2tf32(B[(size_t)(kb + tig + 4) * HC + col]);
        }
#pragma unroll
        for (int mt = 0; mt < 2; mt++) {
            int ra = r0 + mt * 16;
            int rb = ra + 8;
            bool ga = ra < NN, gb = rb < NN;
            uint32_t a0 = ga ? f2tf32(A[(size_t)ra * ICH + kb + tig])     : 0u;
            uint32_t a1 = gb ? f2tf32(A[(size_t)rb * ICH + kb + tig])     : 0u;
            uint32_t a2 = ga ? f2tf32(A[(size_t)ra * ICH + kb + tig + 4]) : 0u;
            uint32_t a3 = gb ? f2tf32(A[(size_t)rb * ICH + kb + tig + 4]) : 0u;
#pragma unroll
            for (int nt = 0; nt < 4; nt++)
                mma_tf32(acc[mt][nt], a0, a1, a2, a3, bf[nt][0], bf[nt][1]);
        }
    }

    __shared__ float sS[128], sD[128];
    if (threadIdx.x < 128) { sS[threadIdx.x] = 0.f; sD[threadIdx.x] = 0.f; }
    __syncthreads();

#pragma unroll
    for (int mt = 0; mt < 2; mt++) {
        int ra = r0 + mt * 16;
        int rb = ra + 8;
        float s0 = 0.f, d0 = 0.f, s1 = 0.f, d1 = 0.f;
#pragma unroll
        for (int nt = 0; nt < 4; nt++) {
            int col = colbase + nt * 8 + 2 * tig;
            float2 v0 = make_float2(acc[mt][nt][0], acc[mt][nt][1]);
            float2 v1 = make_float2(acc[mt][nt][2], acc[mt][nt][3]);
            if (ra < NN) *(float2*)&g_x[(size_t)ra * HC + col] = v0;
            if (rb < NN) *(float2*)&g_x[(size_t)rb * HC + col] = v1;
            float2 as = *(const float2*)&att_s[h * OC + (col - bn)];
            float2 ad = *(const float2*)&att_d[h * OC + (col - bn)];
            s0 += v0.x * as.x + v0.y * as.y;
            d0 += v0.x * ad.x + v0.y * ad.y;
            s1 += v1.x * as.x + v1.y * as.y;
            d1 += v1.x * ad.x + v1.y * ad.y;
        }
#pragma unroll
        for (int off = 1; off <= 2; off <<= 1) {
            s0 += __shfl_xor_sync(0xffffffffu, s0, off);
            d0 += __shfl_xor_sync(0xffffffffu, d0, off);
            s1 += __shfl_xor_sync(0xffffffffu, s1, off);
            d1 += __shfl_xor_sync(0xffffffffu, d1, off);
        }
        if (tig == 0) {
            int rl = wm * 32 + mt * 16 + gid;
            atomicAdd(&sS[rl], s0);     atomicAdd(&sD[rl], d0);
            atomicAdd(&sS[rl + 8], s1); atomicAdd(&sD[rl + 8], d1);
        }
    }
    __syncthreads();
    if (threadIdx.x < 128) {
        int row = bm + threadIdx.x;
        if (row < NN) {
            g_asrc[row * NH + h] = sS[threadIdx.x];
            g_adst[row * NH + h] = sD[threadIdx.x];
        }
    }
}

// ---------------- fused attention gather: 2 warps per dst --------
// Block = 256 threads = 8 warps = 4 dst nodes (NN divisible by 4).
// Warp pair (2j, 2j+1) handles dst; warp member hpair owns heads
// {2*hpair, 2*hpair+1}. Lane: hh=lane>>4 picks head-in-pair, q=lane&15
// picks the channel quad. Per edge each lane does ONE LDG.128 of
// x[src, head*64 + q*4 ..] (warp = contiguous 512B span) and ONE expf.
// Partials: shfl_xor(16) combines the head pair, smem combines warp pairs.
// No global atomics; out written exactly once.
__global__ void __launch_bounds__(256) gather_kernel(float* __restrict__ out,
                                                     const float* __restrict__ bias) {
    const int wb    = threadIdx.x >> 5;       // warp in block 0..7
    const int dloc  = wb >> 1;                // dst slot in block 0..3
    const int hpair = wb & 1;                 // head pair 0:{0,1} 1:{2,3}
    const int dst   = blockIdx.x * 4 + dloc;
    const int lane  = threadIdx.x & 31;
    const int hh    = lane >> 4;
    const int q     = lane & 15;
    const int head  = hpair * 2 + hh;

    __shared__ float4 sacc[4][16];

    const int beg = g_start[dst];
    const int cnt = g_count[dst];
    const float adh = comp4(*(const float4*)&g_adst[dst * NH], head);

    float4 acc = make_float4(0.f, 0.f, 0.f, 0.f);
    float  den = 0.f;

    int    src_n = g_csr[beg];
    float4 as_n  = *(const float4*)&g_asrc[src_n * NH];

    const float4* __restrict__ xq = (const float4*)g_x;
    const int     qoff = head * 16 + q;

    for (int i = 0; i < cnt; i++) {
        int    src = src_n;
        float4 as  = as_n;
        if (i + 1 < cnt) {
            src_n = g_csr[beg + i + 1];
            as_n  = *(const float4*)&g_asrc[src_n * NH];
        }
        float v = comp4(as, head) + adh;
        v = v > 0.f ? v : 0.2f * v;            // leaky_relu slope 0.2
        float ex = __expf(v);                  // no max-shift needed
        den += ex;
        float4 xv = xq[(size_t)src * 64 + qoff];
        acc.x += ex * xv.x;
        acc.y += ex * xv.y;
        acc.z += ex * xv.z;
        acc.w += ex * xv.w;
    }

    float r = 1.0f / den;
    acc.x *= r; acc.y *= r; acc.z *= r; acc.w *= r;

    // combine the two heads within the warp
    acc.x += __shfl_xor_sync(0xffffffffu, acc.x, 16);
    acc.y += __shfl_xor_sync(0xffffffffu, acc.y, 16);
    acc.z += __shfl_xor_sync(0xffffffffu, acc.z, 16);
    acc.w += __shfl_xor_sync(0xffffffffu, acc.w, 16);

    // combine the two warps of the pair via smem
    if (hpair == 1 && lane < 16) sacc[dloc][q] = acc;
    __syncthreads();
    if (hpair == 0 && lane < 16) {
        float4 o = sacc[dloc][q];
        float4 b = *(const float4*)&bias[q * 4];
        o.x = (acc.x + o.x) * 0.25f + b.x;
        o.y = (acc.y + o.y) * 0.25f + b.y;
        o.z = (acc.z + o.z) * 0.25f + b.z;
        o.w = (acc.w + o.w) * 0.25f + b.w;
        *(float4*)&out[(size_t)dst * OC + q * 4] = o;
    }
}

// ---------------- launch ----------------------------------------
extern "C" void kernel_launch(void* const* d_in, const int* in_sizes, int n_in,
                              void* d_out, int out_size) {
    const float* feature    = (const float*)d_in[0];
    const void*  edge_index = d_in[1];
    const float* lin_w      = (const float*)d_in[2];
    const float* att_src    = (const float*)d_in[3];
    const float* att_dst    = (const float*)d_in[4];
    const float* bias       = (const float*)d_in[5];
    float*       out        = (float*)d_out;

    detect_kernel<<<1, 256>>>((const int*)edge_index);
    zero_kernel<<<(NPAD + 255) / 256, 256>>>();

    dim3 ggrid((NN + 127) / 128, NH);
    gemm_kernel<<<ggrid, 256>>>(feature, lin_w, att_src, att_dst);

    hist_kernel<<<(NET + 255) / 256, 256>>>(edge_index);
    scan1_kernel<<<NBLK, SCAN_BLK>>>();
    scan2_kernel<<<1, 64>>>();
    scan3_kernel<<<(NPAD + 255) / 256, 256>>>();
    fill_kernel<<<(NET + 255) / 256, 256>>>(edge_index);

    gather_kernel<<<NN / 4, 256>>>(out, bias);
}

// round 7
// speedup vs baseline: 1.7117x; 1.1779x over previous
#include <cuda_runtime.h>
#include <stdint.h>

// Problem constants (fixed by reference)
#define NN   50000      // nodes
#define NE   800000     // edges (before self loops)
#define NET  850000     // edges + self loops
#define ICH  128        // in channels
#define HC   256        // heads * out = 4*64
#define OC   64         // out channels
#define NH   4          // heads

#define SCAN_BLK 1024
#define NBLK     ((NN + SCAN_BLK - 1) / SCAN_BLK)   // 49
#define NPAD     (NBLK * SCAN_BLK)                  // 50176

// ---------------- device scratch (allocation-free) ----------------
__device__ __align__(16) float g_x[(size_t)NN * HC];   // projected features [N, H*C]
__device__ __align__(16) float g_asrc[NN * NH];        // per-node src logits
__device__ __align__(16) float g_adst[NN * NH];        // per-node dst logits
__device__ int   g_count[NPAD];                        // in-degree per dst
__device__ int   g_start[NPAD];                        // CSR row starts (excl scan)
__device__ int   g_cursor[NPAD];                       // fill cursors
__device__ int   g_csr[NET];                           // src ids grouped by dst
__device__ int   g_bsum[NBLK];                         // scan block sums
__device__ int   g_is64;                               // edge_index dtype flag

// ---------------- helpers ----------------------------------------
__device__ __forceinline__ uint32_t f2tf32(float f) {
    uint32_t u;
    asm("cvt.rna.tf32.f32 %0, %1;" : "=r"(u) : "f"(f));
    return u;
}

__device__ __forceinline__ void mma_tf32(float c[4],
                                         uint32_t a0, uint32_t a1, uint32_t a2, uint32_t a3,
                                         uint32_t b0, uint32_t b1) {
    asm volatile(
        "mma.sync.aligned.m16n8k8.row.col.f32.tf32.tf32.f32 "
        "{%0,%1,%2,%3}, {%4,%5,%6,%7}, {%8,%9}, {%0,%1,%2,%3};"
        : "+f"(c[0]), "+f"(c[1]), "+f"(c[2]), "+f"(c[3])
        : "r"(a0), "r"(a1), "r"(a2), "r"(a3), "r"(b0), "r"(b1));
}

__device__ __forceinline__ void load_edge(const void* idx, int e, int& src, int& dst) {
    if (e < NE) {
        if (g_is64) {
            const long long* p = (const long long*)idx;
            src = (int)p[e];
            dst = (int)p[NE + e];
        } else {
            const int* p = (const int*)idx;
            src = p[e];
            dst = p[NE + e];
        }
    } else {
        src = dst = e - NE;   // self loop
    }
}

__device__ __forceinline__ float lrelu_exp(float v) {
    v = v > 0.f ? v : 0.2f * v;       // leaky_relu slope 0.2
    return __expf(v);                 // no max-shift needed (|v| small)
}

// ---------------- dtype detection -------------------------------
// int64 little-endian node ids < 50000 => every odd 32-bit word zero.
__global__ void detect_kernel(const int* __restrict__ idx32) {
    __shared__ int bad;
    if (threadIdx.x == 0) bad = 0;
    __syncthreads();
    for (int i = threadIdx.x; i < 2048; i += blockDim.x) {
        if (idx32[2 * i + 1] != 0) bad = 1;
    }
    __syncthreads();
    if (threadIdx.x == 0) g_is64 = bad ? 0 : 1;
}

// ---------------- zero counters ----------------------------------
__global__ void zero_kernel() {
    int i = blockIdx.x * blockDim.x + threadIdx.x;
    if (i < NPAD) g_count[i] = 0;
}

// ---------------- histogram of in-degrees ------------------------
__global__ void hist_kernel(const void* __restrict__ idx) {
    int e = blockIdx.x * blockDim.x + threadIdx.x;
    if (e >= NET) return;
    int src, dst;
    load_edge(idx, e, src, dst);
    atomicAdd(&g_count[dst], 1);
}

// ---------------- scan pass 1: per-block inclusive scan ----------
__global__ void __launch_bounds__(SCAN_BLK) scan1_kernel() {
    __shared__ int sh[SCAN_BLK];
    int i = blockIdx.x * SCAN_BLK + threadIdx.x;
    int v = g_count[i];
    sh[threadIdx.x] = v;
    __syncthreads();
#pragma unroll
    for (int off = 1; off < SCAN_BLK; off <<= 1) {
        int t = (threadIdx.x >= off) ? sh[threadIdx.x - off] : 0;
        __syncthreads();
        sh[threadIdx.x] += t;
        __syncthreads();
    }
    g_start[i] = sh[threadIdx.x];           // inclusive scan within block
    if (threadIdx.x == SCAN_BLK - 1) g_bsum[blockIdx.x] = sh[threadIdx.x];
}

// ---------------- scan pass 2: exclusive scan of block sums ------
__global__ void scan2_kernel() {
    __shared__ int sh[64];
    int v = (threadIdx.x < NBLK) ? g_bsum[threadIdx.x] : 0;
    sh[threadIdx.x] = v;
    __syncthreads();
    for (int off = 1; off < 64; off <<= 1) {
        int t = (threadIdx.x >= off) ? sh[threadIdx.x - off] : 0;
        __syncthreads();
        sh[threadIdx.x] += t;
        __syncthreads();
    }
    if (threadIdx.x < NBLK)
        g_bsum[threadIdx.x] = sh[threadIdx.x] - v;   // exclusive
}

// ---------------- scan pass 3: exclusive starts + cursors --------
__global__ void scan3_kernel() {
    int i = blockIdx.x * blockDim.x + threadIdx.x;
    if (i >= NPAD) return;
    int s = g_start[i] - g_count[i] + g_bsum[i / SCAN_BLK];
    g_start[i]  = s;
    g_cursor[i] = s;
}

// ---------------- fill CSR ---------------------------------------
__global__ void fill_kernel(const void* __restrict__ idx) {
    int e = blockIdx.x * blockDim.x + threadIdx.x;
    if (e >= NET) return;
    int src, dst;
    load_edge(idx, e, src, dst);
    int pos = atomicAdd(&g_cursor[dst], 1);
    g_csr[pos] = src;
}

// ---------------- tf32 tensor-core GEMM + fused logits -----------
__global__ void __launch_bounds__(256) gemm_kernel(const float* __restrict__ A,
                                                   const float* __restrict__ B,
                                                   const float* __restrict__ att_s,
                                                   const float* __restrict__ att_d) {
    const int bm   = blockIdx.x * 128;
    const int h    = blockIdx.y;       // head
    const int bn   = h * 64;
    const int wid  = threadIdx.x >> 5;
    const int lane = threadIdx.x & 31;
    const int wm   = wid & 3;
    const int wn   = wid >> 2;
    const int gid  = lane >> 2;
    const int tig  = lane & 3;

    const int colbase = bn + wn * 32;
    const int r0      = bm + wm * 32 + gid;

    float acc[2][4][4];
#pragma unroll
    for (int mt = 0; mt < 2; mt++)
#pragma unroll
        for (int nt = 0; nt < 4; nt++)
#pragma unroll
            for (int c = 0; c < 4; c++) acc[mt][nt][c] = 0.f;

#pragma unroll 2
    for (int kb = 0; kb < ICH; kb += 8) {
        uint32_t bf[4][2];
#pragma unroll
        for (int nt = 0; nt < 4; nt++) {
            int col = colbase + nt * 8 + gid;
            bf[nt][0] = f2tf32(B[(size_t)(kb + tig) * HC + col]);
            bf[nt][1] = f2tf32(B[(size_t)(kb + tig + 4) * HC + col]);
        }
#pragma unroll
        for (int mt = 0; mt < 2; mt++) {
            int ra = r0 + mt * 16;
            int rb = ra + 8;
            bool ga = ra < NN, gb = rb < NN;
            uint32_t a0 = ga ? f2tf32(A[(size_t)ra * ICH + kb + tig])     : 0u;
            uint32_t a1 = gb ? f2tf32(A[(size_t)rb * ICH + kb + tig])     : 0u;
            uint32_t a2 = ga ? f2tf32(A[(size_t)ra * ICH + kb + tig + 4]) : 0u;
            uint32_t a3 = gb ? f2tf32(A[(size_t)rb * ICH + kb + tig + 4]) : 0u;
#pragma unroll
            for (int nt = 0; nt < 4; nt++)
                mma_tf32(acc[mt][nt], a0, a1, a2, a3, bf[nt][0], bf[nt][1]);
        }
    }

    __shared__ float sS[128], sD[128];
    if (threadIdx.x < 128) { sS[threadIdx.x] = 0.f; sD[threadIdx.x] = 0.f; }
    __syncthreads();

#pragma unroll
    for (int mt = 0; mt < 2; mt++) {
        int ra = r0 + mt * 16;
        int rb = ra + 8;
        float s0 = 0.f, d0 = 0.f, s1 = 0.f, d1 = 0.f;
#pragma unroll
        for (int nt = 0; nt < 4; nt++) {
            int col = colbase + nt * 8 + 2 * tig;
            float2 v0 = make_float2(acc[mt][nt][0], acc[mt][nt][1]);
            float2 v1 = make_float2(acc[mt][nt][2], acc[mt][nt][3]);
            if (ra < NN) *(float2*)&g_x[(size_t)ra * HC + col] = v0;
            if (rb < NN) *(float2*)&g_x[(size_t)rb * HC + col] = v1;
            float2 as = *(const float2*)&att_s[h * OC + (col - bn)];
            float2 ad = *(const float2*)&att_d[h * OC + (col - bn)];
            s0 += v0.x * as.x + v0.y * as.y;
            d0 += v0.x * ad.x + v0.y * ad.y;
            s1 += v1.x * as.x + v1.y * as.y;
            d1 += v1.x * ad.x + v1.y * ad.y;
        }
#pragma unroll
        for (int off = 1; off <= 2; off <<= 1) {
            s0 += __shfl_xor_sync(0xffffffffu, s0, off);
            d0 += __shfl_xor_sync(0xffffffffu, d0, off);
            s1 += __shfl_xor_sync(0xffffffffu, s1, off);
            d1 += __shfl_xor_sync(0xffffffffu, d1, off);
        }
        if (tig == 0) {
            int rl = wm * 32 + mt * 16 + gid;
            atomicAdd(&sS[rl], s0);     atomicAdd(&sD[rl], d0);
            atomicAdd(&sS[rl + 8], s1); atomicAdd(&sD[rl + 8], d1);
        }
    }
    __syncthreads();
    if (threadIdx.x < 128) {
        int row = bm + threadIdx.x;
        if (row < NN) {
            g_asrc[row * NH + h] = sS[threadIdx.x];
            g_adst[row * NH + h] = sD[threadIdx.x];
        }
    }
}

// ---------------- fused attention gather: 2 warps per dst --------
// 4-edge unrolled hot loop: batch 4 csr loads -> 4 independent LDG.128
// x gathers + 4 scalar logit loads in flight (MLP=4) before any consume.
// Lane owns 16B of x[src, head*64 + 4q ..]; warp covers a contiguous
// 512B span of its head pair. shfl_xor(16) + smem combine; no atomics.
__global__ void __launch_bounds__(256) gather_kernel(float* __restrict__ out,
                                                     const float* __restrict__ bias) {
    const int wb    = threadIdx.x >> 5;       // warp in block 0..7
    const int dloc  = wb >> 1;                // dst slot in block 0..3
    const int hpair = wb & 1;                 // head pair 0:{0,1} 1:{2,3}
    const int dst   = blockIdx.x * 4 + dloc;
    const int lane  = threadIdx.x & 31;
    const int hh    = lane >> 4;
    const int q     = lane & 15;
    const int head  = hpair * 2 + hh;

    __shared__ float4 sacc[4][16];

    const int beg = g_start[dst];
    const int cnt = g_count[dst];
    const float adh = g_adst[dst * NH + head];

    float4 acc = make_float4(0.f, 0.f, 0.f, 0.f);
    float  den = 0.f;

    const float4* __restrict__ xq  = (const float4*)g_x;
    const float*  __restrict__ asr = g_asrc;
    const int     qoff = head * 16 + q;

    int i = 0;
    for (; i + 4 <= cnt; i += 4) {
        int s0 = g_csr[beg + i];
        int s1 = g_csr[beg + i + 1];
        int s2 = g_csr[beg + i + 2];
        int s3 = g_csr[beg + i + 3];
        // issue all 4 big gathers + 4 scalar loads before consuming
        float4 x0 = xq[(size_t)s0 * 64 + qoff];
        float4 x1 = xq[(size_t)s1 * 64 + qoff];
        float4 x2 = xq[(size_t)s2 * 64 + qoff];
        float4 x3 = xq[(size_t)s3 * 64 + qoff];
        float  a0 = asr[s0 * NH + head];
        float  a1 = asr[s1 * NH + head];
        float  a2 = asr[s2 * NH + head];
        float  a3 = asr[s3 * NH + head];
        float e0 = lrelu_exp(a0 + adh);
        float e1 = lrelu_exp(a1 + adh);
        float e2 = lrelu_exp(a2 + adh);
        float e3 = lrelu_exp(a3 + adh);
        den += (e0 + e1) + (e2 + e3);
        acc.x += e0 * x0.x + e1 * x1.x + e2 * x2.x + e3 * x3.x;
        acc.y += e0 * x0.y + e1 * x1.y + e2 * x2.y + e3 * x3.y;
        acc.z += e0 * x0.z + e1 * x1.z + e2 * x2.z + e3 * x3.z;
        acc.w += e0 * x0.w + e1 * x1.w + e2 * x2.w + e3 * x3.w;
    }
    for (; i < cnt; i++) {
        int    s  = g_csr[beg + i];
        float4 xv = xq[(size_t)s * 64 + qoff];
        float  ex = lrelu_exp(asr[s * NH + head] + adh);
        den += ex;
        acc.x += ex * xv.x;
        acc.y += ex * xv.y;
        acc.z += ex * xv.z;
        acc.w += ex * xv.w;
    }

    float r = 1.0f / den;
    acc.x *= r; acc.y *= r; acc.z *= r; acc.w *= r;

    // combine the two heads within the warp
    acc.x += __shfl_xor_sync(0xffffffffu, acc.x, 16);
    acc.y += __shfl_xor_sync(0xffffffffu, acc.y, 16);
    acc.z += __shfl_xor_sync(0xffffffffu, acc.z, 16);
    acc.w += __shfl_xor_sync(0xffffffffu, acc.w, 16);

    // combine the two warps of the pair via smem
    if (hpair == 1 && lane < 16) sacc[dloc][q] = acc;
    __syncthreads();
    if (hpair == 0 && lane < 16) {
        float4 o = sacc[dloc][q];
        float4 b = *(const float4*)&bias[q * 4];
        o.x = (acc.x + o.x) * 0.25f + b.x;
        o.y = (acc.y + o.y) * 0.25f + b.y;
        o.z = (acc.z + o.z) * 0.25f + b.z;
        o.w = (acc.w + o.w) * 0.25f + b.w;
        *(float4*)&out[(size_t)dst * OC + q * 4] = o;
    }
}

// ---------------- launch ----------------------------------------
extern "C" void kernel_launch(void* const* d_in, const int* in_sizes, int n_in,
                              void* d_out, int out_size) {
    const float* feature    = (const float*)d_in[0];
    const void*  edge_index = d_in[1];
    const float* lin_w      = (const float*)d_in[2];
    const float* att_src    = (const float*)d_in[3];
    const float* att_dst    = (const float*)d_in[4];
    const float* bias       = (const float*)d_in[5];
    float*       out        = (float*)d_out;

    detect_kernel<<<1, 256>>>((const int*)edge_index);
    zero_kernel<<<(NPAD + 255) / 256, 256>>>();

    dim3 ggrid((NN + 127) / 128, NH);
    gemm_kernel<<<ggrid, 256>>>(feature, lin_w, att_src, att_dst);

    hist_kernel<<<(NET + 255) / 256, 256>>>(edge_index);
    scan1_kernel<<<NBLK, SCAN_BLK>>>();
    scan2_kernel<<<1, 64>>>();
    scan3_kernel<<<(NPAD + 255) / 256, 256>>>();
    fill_kernel<<<(NET + 255) / 256, 256>>>(edge_index);

    gather_kernel<<<NN / 4, 256>>>(out, bias);
}

// round 8
// speedup vs baseline: 1.9766x; 1.1548x over previous
#include <cuda_runtime.h>
#include <cuda_fp16.h>
#include <stdint.h>

// Problem constants (fixed by reference)
#define NN   50000      // nodes
#define NE   800000     // edges (before self loops)
#define NET  850000     // edges + self loops
#define ICH  128        // in channels
#define HC   256        // heads * out = 4*64
#define OC   64         // out channels
#define NH   4          // heads

#define SCAN_BLK 1024
#define NBLK     ((NN + SCAN_BLK - 1) / SCAN_BLK)   // 49
#define NPAD     (NBLK * SCAN_BLK)                  // 50176

// ---------------- device scratch (allocation-free) ----------------
__device__ __align__(16) __half g_xh[(size_t)NN * HC]; // projected features, fp16
__device__ __align__(16) float g_asrc[NN * NH];        // per-node src logits
__device__ __align__(16) float g_adst[NN * NH];        // per-node dst logits
__device__ int   g_count[NPAD];                        // in-degree per dst
__device__ int   g_start[NPAD];                        // CSR row starts (excl scan)
__device__ int   g_cursor[NPAD];                       // fill cursors
__device__ int   g_csr[NET];                           // src ids grouped by dst
__device__ int   g_bsum[NBLK];                         // scan block sums
__device__ int   g_is64;                               // edge_index dtype flag

// ---------------- helpers ----------------------------------------
__device__ __forceinline__ uint32_t f2tf32(float f) {
    uint32_t u;
    asm("cvt.rna.tf32.f32 %0, %1;" : "=r"(u) : "f"(f));
    return u;
}

__device__ __forceinline__ void mma_tf32(float c[4],
                                         uint32_t a0, uint32_t a1, uint32_t a2, uint32_t a3,
                                         uint32_t b0, uint32_t b1) {
    asm volatile(
        "mma.sync.aligned.m16n8k8.row.col.f32.tf32.tf32.f32 "
        "{%0,%1,%2,%3}, {%4,%5,%6,%7}, {%8,%9}, {%0,%1,%2,%3};"
        : "+f"(c[0]), "+f"(c[1]), "+f"(c[2]), "+f"(c[3])
        : "r"(a0), "r"(a1), "r"(a2), "r"(a3), "r"(b0), "r"(b1));
}

__device__ __forceinline__ void load_edge(const void* idx, int e, int& src, int& dst) {
    if (e < NE) {
        if (g_is64) {
            const long long* p = (const long long*)idx;
            src = (int)p[e];
            dst = (int)p[NE + e];
        } else {
            const int* p = (const int*)idx;
            src = p[e];
            dst = p[NE + e];
        }
    } else {
        src = dst = e - NE;   // self loop
    }
}

__device__ __forceinline__ float lrelu_exp(float v) {
    v = v > 0.f ? v : 0.2f * v;       // leaky_relu slope 0.2
    return __expf(v);                 // no max-shift needed (|v| small)
}

// ---------------- dtype detection -------------------------------
__global__ void detect_kernel(const int* __restrict__ idx32) {
    __shared__ int bad;
    if (threadIdx.x == 0) bad = 0;
    __syncthreads();
    for (int i = threadIdx.x; i < 2048; i += blockDim.x) {
        if (idx32[2 * i + 1] != 0) bad = 1;
    }
    __syncthreads();
    if (threadIdx.x == 0) g_is64 = bad ? 0 : 1;
}

// ---------------- zero counters ----------------------------------
__global__ void zero_kernel() {
    int i = blockIdx.x * blockDim.x + threadIdx.x;
    if (i < NPAD) g_count[i] = 0;
}

// ---------------- histogram of in-degrees (4 edges/thread) -------
__global__ void hist_kernel(const void* __restrict__ idx) {
    int e0 = (blockIdx.x * blockDim.x + threadIdx.x) * 4;
    int s[4], d[4];
#pragma unroll
    for (int j = 0; j < 4; j++)
        if (e0 + j < NET) load_edge(idx, e0 + j, s[j], d[j]);
#pragma unroll
    for (int j = 0; j < 4; j++)
        if (e0 + j < NET) atomicAdd(&g_count[d[j]], 1);
}

// ---------------- scan pass 1: per-block inclusive scan ----------
__global__ void __launch_bounds__(SCAN_BLK) scan1_kernel() {
    __shared__ int sh[SCAN_BLK];
    int i = blockIdx.x * SCAN_BLK + threadIdx.x;
    int v = g_count[i];
    sh[threadIdx.x] = v;
    __syncthreads();
#pragma unroll
    for (int off = 1; off < SCAN_BLK; off <<= 1) {
        int t = (threadIdx.x >= off) ? sh[threadIdx.x - off] : 0;
        __syncthreads();
        sh[threadIdx.x] += t;
        __syncthreads();
    }
    g_start[i] = sh[threadIdx.x];
    if (threadIdx.x == SCAN_BLK - 1) g_bsum[blockIdx.x] = sh[threadIdx.x];
}

// ---------------- scan pass 2: exclusive scan of block sums ------
__global__ void scan2_kernel() {
    __shared__ int sh[64];
    int v = (threadIdx.x < NBLK) ? g_bsum[threadIdx.x] : 0;
    sh[threadIdx.x] = v;
    __syncthreads();
    for (int off = 1; off < 64; off <<= 1) {
        int t = (threadIdx.x >= off) ? sh[threadIdx.x - off] : 0;
        __syncthreads();
        sh[threadIdx.x] += t;
        __syncthreads();
    }
    if (threadIdx.x < NBLK)
        g_bsum[threadIdx.x] = sh[threadIdx.x] - v;
}

// ---------------- scan pass 3: exclusive starts + cursors --------
__global__ void scan3_kernel() {
    int i = blockIdx.x * blockDim.x + threadIdx.x;
    if (i >= NPAD) return;
    int s = g_start[i] - g_count[i] + g_bsum[i / SCAN_BLK];
    g_start[i]  = s;
    g_cursor[i] = s;
}

// ---------------- fill CSR (4 edges/thread) ----------------------
__global__ void fill_kernel(const void* __restrict__ idx) {
    int e0 = (blockIdx.x * blockDim.x + threadIdx.x) * 4;
    int s[4], d[4];
#pragma unroll
    for (int j = 0; j < 4; j++)
        if (e0 + j < NET) load_edge(idx, e0 + j, s[j], d[j]);
#pragma unroll
    for (int j = 0; j < 4; j++)
        if (e0 + j < NET) {
            int pos = atomicAdd(&g_cursor[d[j]], 1);
            g_csr[pos] = s[j];
        }
}

// ---------------- tf32 tensor-core GEMM + fused logits -----------
// x stored as fp16 (g_xh): its only consumer is the gather, and fp16
// half-ulp 2^-11 keeps the output well under the 1e-3 threshold.
__global__ void __launch_bounds__(256) gemm_kernel(const float* __restrict__ A,
                                                   const float* __restrict__ B,
                                                   const float* __restrict__ att_s,
                                                   const float* __restrict__ att_d) {
    const int bm   = blockIdx.x * 128;
    const int h    = blockIdx.y;       // head
    const int bn   = h * 64;
    const int wid  = threadIdx.x >> 5;
    const int lane = threadIdx.x & 31;
    const int wm   = wid & 3;
    const int wn   = wid >> 2;
    const int gid  = lane >> 2;
    const int tig  = lane & 3;

    const int colbase = bn + wn * 32;
    const int r0      = bm + wm * 32 + gid;

    float acc[2][4][4];
#pragma unroll
    for (int mt = 0; mt < 2; mt++)
#pragma unroll
        for (int nt = 0; nt < 4; nt++)
#pragma unroll
            for (int c = 0; c < 4; c++) acc[mt][nt][c] = 0.f;

#pragma unroll 2
    for (int kb = 0; kb < ICH; kb += 8) {
        uint32_t bf[4][2];
#pragma unroll
        for (int nt = 0; nt < 4; nt++) {
            int col = colbase + nt * 8 + gid;
            bf[nt][0] = f2tf32(B[(size_t)(kb + tig) * HC + col]);
            bf[nt][1] = f2tf32(B[(size_t)(kb + tig + 4) * HC + col]);
        }
#pragma unroll
        for (int mt = 0; mt < 2; mt++) {
            int ra = r0 + mt * 16;
            int rb = ra + 8;
            bool ga = ra < NN, gb = rb < NN;
            uint32_t a0 = ga ? f2tf32(A[(size_t)ra * ICH + kb + tig])     : 0u;
            uint32_t a1 = gb ? f2tf32(A[(size_t)rb * ICH + kb + tig])     : 0u;
            uint32_t a2 = ga ? f2tf32(A[(size_t)ra * ICH + kb + tig + 4]) : 0u;
            uint32_t a3 = gb ? f2tf32(A[(size_t)rb * ICH + kb + tig + 4]) : 0u;
#pragma unroll
            for (int nt = 0; nt < 4; nt++)
                mma_tf32(acc[mt][nt], a0, a1, a2, a3, bf[nt][0], bf[nt][1]);
        }
    }

    __shared__ float sS[128], sD[128];
    if (threadIdx.x < 128) { sS[threadIdx.x] = 0.f; sD[threadIdx.x] = 0.f; }
    __syncthreads();

#pragma unroll
    for (int mt = 0; mt < 2; mt++) {
        int ra = r0 + mt * 16;
        int rb = ra + 8;
        float s0 = 0.f, d0 = 0.f, s1 = 0.f, d1 = 0.f;
#pragma unroll
        for (int nt = 0; nt < 4; nt++) {
            int col = colbase + nt * 8 + 2 * tig;
            float2 v0 = make_float2(acc[mt][nt][0], acc[mt][nt][1]);
            float2 v1 = make_float2(acc[mt][nt][2], acc[mt][nt][3]);
            if (ra < NN) *(__half2*)&g_xh[(size_t)ra * HC + col] = __float22half2_rn(v0);
            if (rb < NN) *(__half2*)&g_xh[(size_t)rb * HC + col] = __float22half2_rn(v1);
            float2 as = *(const float2*)&att_s[h * OC + (col - bn)];
            float2 ad = *(const float2*)&att_d[h * OC + (col - bn)];
            s0 += v0.x * as.x + v0.y * as.y;
            d0 += v0.x * ad.x + v0.y * ad.y;
            s1 += v1.x * as.x + v1.y * as.y;
            d1 += v1.x * ad.x + v1.y * ad.y;
        }
#pragma unroll
        for (int off = 1; off <= 2; off <<= 1) {
            s0 += __shfl_xor_sync(0xffffffffu, s0, off);
            d0 += __shfl_xor_sync(0xffffffffu, d0, off);
            s1 += __shfl_xor_sync(0xffffffffu, s1, off);
            d1 += __shfl_xor_sync(0xffffffffu, d1, off);
        }
        if (tig == 0) {
            int rl = wm * 32 + mt * 16 + gid;
            atomicAdd(&sS[rl], s0);     atomicAdd(&sD[rl], d0);
            atomicAdd(&sS[rl + 8], s1); atomicAdd(&sD[rl + 8], d1);
        }
    }
    __syncthreads();
    if (threadIdx.x < 128) {
        int row = bm + threadIdx.x;
        if (row < NN) {
            g_asrc[row * NH + h] = sS[threadIdx.x];
            g_adst[row * NH + h] = sD[threadIdx.x];
        }
    }
}

// ---------------- fused attention gather: 1 warp per dst ---------
// fp16 x row = 512B = exactly one warp LDG.128. Lane owns head=lane>>3,
// channels (lane&7)*8..+8 (one int4 = 8 halves). Per edge per lane:
// 1 LDG.128 + 1 scalar logit load + 1 expf. 4-edge unroll keeps MLP=4.
// Head combine: shfl_xor(8), shfl_xor(16) after per-head normalize.
__global__ void __launch_bounds__(256) gather_kernel(float* __restrict__ out,
                                                     const float* __restrict__ bias) {
    const int warp = threadIdx.x >> 5;
    const int dst  = blockIdx.x * 8 + warp;
    const int lane = threadIdx.x & 31;
    const int head = lane >> 3;

    const int beg = g_start[dst];
    const int cnt = g_count[dst];
    const float adh = g_adst[dst * NH + head];

    float a0f = 0.f, a1f = 0.f, a2f = 0.f, a3f = 0.f;
    float a4f = 0.f, a5f = 0.f, a6f = 0.f, a7f = 0.f;
    float den = 0.f;

    const int4* __restrict__ xr = (const int4*)g_xh;   // 32 int4 per row
    const float* __restrict__ asr = g_asrc;

    int i = 0;
    for (; i + 4 <= cnt; i += 4) {
        int s0 = g_csr[beg + i];
        int s1 = g_csr[beg + i + 1];
        int s2 = g_csr[beg + i + 2];
        int s3 = g_csr[beg + i + 3];
        int4 x0 = xr[(size_t)s0 * 32 + lane];
        int4 x1 = xr[(size_t)s1 * 32 + lane];
        int4 x2 = xr[(size_t)s2 * 32 + lane];
        int4 x3 = xr[(size_t)s3 * 32 + lane];
        float l0 = asr[s0 * NH + head];
        float l1 = asr[s1 * NH + head];
        float l2 = asr[s2 * NH + head];
        float l3 = asr[s3 * NH + head];
        float e0 = lrelu_exp(l0 + adh);
        float e1 = lrelu_exp(l1 + adh);
        float e2 = lrelu_exp(l2 + adh);
        float e3 = lrelu_exp(l3 + adh);
        den += (e0 + e1) + (e2 + e3);
#define ACC_EDGE(X, E) do {                                            \
        float2 f0 = __half22float2(*(const __half2*)&(X).x);           \
        float2 f1 = __half22float2(*(const __half2*)&(X).y);           \
        float2 f2 = __half22float2(*(const __half2*)&(X).z);           \
        float2 f3 = __half22float2(*(const __half2*)&(X).w);           \
        a0f += (E) * f0.x; a1f += (E) * f0.y;                          \
        a2f += (E) * f1.x; a3f += (E) * f1.y;                          \
        a4f += (E) * f2.x; a5f += (E) * f2.y;                          \
        a6f += (E) * f3.x; a7f += (E) * f3.y;                          \
    } while (0)
        ACC_EDGE(x0, e0);
        ACC_EDGE(x1, e1);
        ACC_EDGE(x2, e2);
        ACC_EDGE(x3, e3);
    }
    for (; i < cnt; i++) {
        int s = g_csr[beg + i];
        int4 xv = xr[(size_t)s * 32 + lane];
        float ex = lrelu_exp(asr[s * NH + head] + adh);
        den += ex;
        ACC_EDGE(xv, ex);
    }
#undef ACC_EDGE

    float r = 0.25f / den;
    a0f *= r; a1f *= r; a2f *= r; a3f *= r;
    a4f *= r; a5f *= r; a6f *= r; a7f *= r;

    // sum across the 4 heads (lane groups of 8)
#pragma unroll
    for (int off = 8; off <= 16; off <<= 1) {
        a0f += __shfl_xor_sync(0xffffffffu, a0f, off);
        a1f += __shfl_xor_sync(0xffffffffu, a1f, off);
        a2f += __shfl_xor_sync(0xffffffffu, a2f, off);
        a3f += __shfl_xor_sync(0xffffffffu, a3f, off);
        a4f += __shfl_xor_sync(0xffffffffu, a4f, off);
        a5f += __shfl_xor_sync(0xffffffffu, a5f, off);
        a6f += __shfl_xor_sync(0xffffffffu, a6f, off);
        a7f += __shfl_xor_sync(0xffffffffu, a7f, off);
    }

    if (lane < 8) {
        const float* bq = &bias[lane * 8];
        float4 o0 = make_float4(a0f + bq[0], a1f + bq[1], a2f + bq[2], a3f + bq[3]);
        float4 o1 = make_float4(a4f + bq[4], a5f + bq[5], a6f + bq[6], a7f + bq[7]);
        *(float4*)&out[(size_t)dst * OC + lane * 8]     = o0;
        *(float4*)&out[(size_t)dst * OC + lane * 8 + 4] = o1;
    }
}

// ---------------- launch ----------------------------------------
extern "C" void kernel_launch(void* const* d_in, const int* in_sizes, int n_in,
                              void* d_out, int out_size) {
    const float* feature    = (const float*)d_in[0];
    const void*  edge_index = d_in[1];
    const float* lin_w      = (const float*)d_in[2];
    const float* att_src    = (const float*)d_in[3];
    const float* att_dst    = (const float*)d_in[4];
    const float* bias       = (const float*)d_in[5];
    float*       out        = (float*)d_out;

    detect_kernel<<<1, 256>>>((const int*)edge_index);
    zero_kernel<<<(NPAD + 255) / 256, 256>>>();

    dim3 ggrid((NN + 127) / 128, NH);
    gemm_kernel<<<ggrid, 256>>>(feature, lin_w, att_src, att_dst);

    hist_kernel<<<(NET + 1023) / 1024, 256>>>(edge_index);
    scan1_kernel<<<NBLK, SCAN_BLK>>>();
    scan2_kernel<<<1, 64>>>();
    scan3_kernel<<<(NPAD + 255) / 256, 256>>>();
    fill_kernel<<<(NET + 1023) / 1024, 256>>>(edge_index);

    gather_kernel<<<NN / 8, 256>>>(out, bias);
}

// round 9
// speedup vs baseline: 2.1500x; 1.0877x over previous
#include <cuda_runtime.h>
#include <cuda_fp16.h>
#include <stdint.h>

// Problem constants (fixed by reference)
#define NN   50000      // nodes
#define NE   800000     // edges (before self loops)
#define NET  850000     // edges + self loops
#define ICH  128        // in channels
#define HC   256        // heads * out = 4*64
#define OC   64         // out channels
#define NH   4          // heads

#define SCAN_BLK 1024
#define NBLK     ((NN + SCAN_BLK - 1) / SCAN_BLK)   // 49
#define NPAD     (NBLK * SCAN_BLK)                  // 50176

// ---------------- device scratch (allocation-free) ----------------
__device__ __align__(16) __half g_xh[(size_t)NN * HC]; // projected features, fp16
__device__ __align__(16) float g_asrc[NN * NH];        // per-node src logits
__device__ __align__(16) float g_adst[NN * NH];        // per-node dst logits
__device__ int   g_count[NPAD];                        // in-degree per dst
__device__ int   g_start[NPAD];                        // CSR row starts (excl scan)
__device__ int   g_cursor[NPAD];                       // fill cursors
__device__ int   g_csr[NET];                           // src ids grouped by dst
__device__ int   g_bsum[NBLK];                         // scan block sums
__device__ int   g_is64;                               // edge_index dtype flag

// ---------------- helpers ----------------------------------------
__device__ __forceinline__ uint32_t f2tf32(float f) {
    uint32_t u;
    asm("cvt.rna.tf32.f32 %0, %1;" : "=r"(u) : "f"(f));
    return u;
}

__device__ __forceinline__ void mma_tf32(float c[4],
                                         uint32_t a0, uint32_t a1, uint32_t a2, uint32_t a3,
                                         uint32_t b0, uint32_t b1) {
    asm volatile(
        "mma.sync.aligned.m16n8k8.row.col.f32.tf32.tf32.f32 "
        "{%0,%1,%2,%3}, {%4,%5,%6,%7}, {%8,%9}, {%0,%1,%2,%3};"
        : "+f"(c[0]), "+f"(c[1]), "+f"(c[2]), "+f"(c[3])
        : "r"(a0), "r"(a1), "r"(a2), "r"(a3), "r"(b0), "r"(b1));
}

__device__ __forceinline__ void load_edge(const void* idx, int e, int& src, int& dst) {
    if (e < NE) {
        if (g_is64) {
            const long long* p = (const long long*)idx;
            src = (int)p[e];
            dst = (int)p[NE + e];
        } else {
            const int* p = (const int*)idx;
            src = p[e];
            dst = p[NE + e];
        }
    } else {
        src = dst = e - NE;   // self loop
    }
}

__device__ __forceinline__ int load_dst(const void* idx, int e) {
    if (e < NE) {
        if (g_is64) return (int)((const long long*)idx)[NE + e];
        return ((const int*)idx)[NE + e];
    }
    return e - NE;
}

__device__ __forceinline__ float lrelu_exp(float v) {
    v = v > 0.f ? v : 0.2f * v;       // leaky_relu slope 0.2
    return __expf(v);                 // no max-shift needed (|v| small)
}

// ---------------- dtype detection -------------------------------
__global__ void detect_kernel(const int* __restrict__ idx32) {
    __shared__ int bad;
    if (threadIdx.x == 0) bad = 0;
    __syncthreads();
    for (int i = threadIdx.x; i < 2048; i += blockDim.x) {
        if (idx32[2 * i + 1] != 0) bad = 1;
    }
    __syncthreads();
    if (threadIdx.x == 0) g_is64 = bad ? 0 : 1;
}

// ---------------- zero counters ----------------------------------
__global__ void zero_kernel() {
    int i = blockIdx.x * blockDim.x + threadIdx.x;
    if (i < NPAD) g_count[i] = 0;
}

// ---------------- histogram of in-degrees (4 edges/thread, dst only)
__global__ void hist_kernel(const void* __restrict__ idx) {
    int e0 = (blockIdx.x * blockDim.x + threadIdx.x) * 4;
    int d[4];
#pragma unroll
    for (int j = 0; j < 4; j++)
        if (e0 + j < NET) d[j] = load_dst(idx, e0 + j);
#pragma unroll
    for (int j = 0; j < 4; j++)
        if (e0 + j < NET) atomicAdd(&g_count[d[j]], 1);
}

// ---------------- scan pass 1: per-block inclusive scan ----------
__global__ void __launch_bounds__(SCAN_BLK) scan1_kernel() {
    __shared__ int sh[SCAN_BLK];
    int i = blockIdx.x * SCAN_BLK + threadIdx.x;
    int v = g_count[i];
    sh[threadIdx.x] = v;
    __syncthreads();
#pragma unroll
    for (int off = 1; off < SCAN_BLK; off <<= 1) {
        int t = (threadIdx.x >= off) ? sh[threadIdx.x - off] : 0;
        __syncthreads();
        sh[threadIdx.x] += t;
        __syncthreads();
    }
    g_start[i] = sh[threadIdx.x];
    if (threadIdx.x == SCAN_BLK - 1) g_bsum[blockIdx.x] = sh[threadIdx.x];
}

// ---------------- scan pass 2: exclusive scan of block sums ------
__global__ void scan2_kernel() {
    __shared__ int sh[64];
    int v = (threadIdx.x < NBLK) ? g_bsum[threadIdx.x] : 0;
    sh[threadIdx.x] = v;
    __syncthreads();
    for (int off = 1; off < 64; off <<= 1) {
        int t = (threadIdx.x >= off) ? sh[threadIdx.x - off] : 0;
        __syncthreads();
        sh[threadIdx.x] += t;
        __syncthreads();
    }
    if (threadIdx.x < NBLK)
        g_bsum[threadIdx.x] = sh[threadIdx.x] - v;
}

// ---------------- scan pass 3: exclusive starts + cursors --------
__global__ void scan3_kernel() {
    int i = blockIdx.x * blockDim.x + threadIdx.x;
    if (i >= NPAD) return;
    int s = g_start[i] - g_count[i] + g_bsum[i / SCAN_BLK];
    g_start[i]  = s;
    g_cursor[i] = s;
}

// ---------------- fill CSR (4 edges/thread) ----------------------
__global__ void fill_kernel(const void* __restrict__ idx) {
    int e0 = (blockIdx.x * blockDim.x + threadIdx.x) * 4;
    int s[4], d[4];
#pragma unroll
    for (int j = 0; j < 4; j++)
        if (e0 + j < NET) load_edge(idx, e0 + j, s[j], d[j]);
#pragma unroll
    for (int j = 0; j < 4; j++)
        if (e0 + j < NET) {
            int pos = atomicAdd(&g_cursor[d[j]], 1);
            g_csr[pos] = s[j];
        }
}

// ---------------- tf32 tensor-core GEMM + fused logits -----------
__global__ void __launch_bounds__(256) gemm_kernel(const float* __restrict__ A,
                                                   const float* __restrict__ B,
                                                   const float* __restrict__ att_s,
                                                   const float* __restrict__ att_d) {
    const int bm   = blockIdx.x * 128;
    const int h    = blockIdx.y;       // head
    const int bn   = h * 64;
    const int wid  = threadIdx.x >> 5;
    const int lane = threadIdx.x & 31;
    const int wm   = wid & 3;
    const int wn   = wid >> 2;
    const int gid  = lane >> 2;
    const int tig  = lane & 3;

    const int colbase = bn + wn * 32;
    const int r0      = bm + wm * 32 + gid;

    float acc[2][4][4];
#pragma unroll
    for (int mt = 0; mt < 2; mt++)
#pragma unroll
        for (int nt = 0; nt < 4; nt++)
#pragma unroll
            for (int c = 0; c < 4; c++) acc[mt][nt][c] = 0.f;

#pragma unroll 2
    for (int kb = 0; kb < ICH; kb += 8) {
        uint32_t bf[4][2];
#pragma unroll
        for (int nt = 0; nt < 4; nt++) {
            int col = colbase + nt * 8 + gid;
            bf[nt][0] = f2tf32(B[(size_t)(kb + tig) * HC + col]);
            bf[nt][1] = f2tf32(B[(size_t)(kb + tig + 4) * HC + col]);
        }
#pragma unroll
        for (int mt = 0; mt < 2; mt++) {
            int ra = r0 + mt * 16;
            int rb = ra + 8;
            bool ga = ra < NN, gb = rb < NN;
            uint32_t a0 = ga ? f2tf32(A[(size_t)ra * ICH + kb + tig])     : 0u;
            uint32_t a1 = gb ? f2tf32(A[(size_t)rb * ICH + kb + tig])     : 0u;
            uint32_t a2 = ga ? f2tf32(A[(size_t)ra * ICH + kb + tig + 4]) : 0u;
            uint32_t a3 = gb ? f2tf32(A[(size_t)rb * ICH + kb + tig + 4]) : 0u;
#pragma unroll
            for (int nt = 0; nt < 4; nt++)
                mma_tf32(acc[mt][nt], a0, a1, a2, a3, bf[nt][0], bf[nt][1]);
        }
    }

    __shared__ float sS[128], sD[128];
    if (threadIdx.x < 128) { sS[threadIdx.x] = 0.f; sD[threadIdx.x] = 0.f; }
    __syncthreads();

#pragma unroll
    for (int mt = 0; mt < 2; mt++) {
        int ra = r0 + mt * 16;
        int rb = ra + 8;
        float s0 = 0.f, d0 = 0.f, s1 = 0.f, d1 = 0.f;
#pragma unroll
        for (int nt = 0; nt < 4; nt++) {
            int col = colbase + nt * 8 + 2 * tig;
            float2 v0 = make_float2(acc[mt][nt][0], acc[mt][nt][1]);
            float2 v1 = make_float2(acc[mt][nt][2], acc[mt][nt][3]);
            if (ra < NN) *(__half2*)&g_xh[(size_t)ra * HC + col] = __float22half2_rn(v0);
            if (rb < NN) *(__half2*)&g_xh[(size_t)rb * HC + col] = __float22half2_rn(v1);
            float2 as = *(const float2*)&att_s[h * OC + (col - bn)];
            float2 ad = *(const float2*)&att_d[h * OC + (col - bn)];
            s0 += v0.x * as.x + v0.y * as.y;
            d0 += v0.x * ad.x + v0.y * ad.y;
            s1 += v1.x * as.x + v1.y * as.y;
            d1 += v1.x * ad.x + v1.y * ad.y;
        }
#pragma unroll
        for (int off = 1; off <= 2; off <<= 1) {
            s0 += __shfl_xor_sync(0xffffffffu, s0, off);
            d0 += __shfl_xor_sync(0xffffffffu, d0, off);
            s1 += __shfl_xor_sync(0xffffffffu, s1, off);
            d1 += __shfl_xor_sync(0xffffffffu, d1, off);
        }
        if (tig == 0) {
            int rl = wm * 32 + mt * 16 + gid;
            atomicAdd(&sS[rl], s0);     atomicAdd(&sD[rl], d0);
            atomicAdd(&sS[rl + 8], s1); atomicAdd(&sD[rl + 8], d1);
        }
    }
    __syncthreads();
    if (threadIdx.x < 128) {
        int row = bm + threadIdx.x;
        if (row < NN) {
            g_asrc[row * NH + h] = sS[threadIdx.x];
            g_adst[row * NH + h] = sD[threadIdx.x];
        }
    }
}

// ---------------- fused attention gather: 1 warp per dst ---------
// fp16 x row = 512B = exactly one warp LDG.128. Lane owns head=lane>>3,
// 8 channels (one int4). 8-edge unroll (MLP=8) + 4 + scalar tails.
#define ACC_EDGE(X, E) do {                                            \
        float2 f0 = __half22float2(*(const __half2*)&(X).x);           \
        float2 f1 = __half22float2(*(const __half2*)&(X).y);           \
        float2 f2 = __half22float2(*(const __half2*)&(X).z);           \
        float2 f3 = __half22float2(*(const __half2*)&(X).w);           \
        a0f += (E) * f0.x; a1f += (E) * f0.y;                          \
        a2f += (E) * f1.x; a3f += (E) * f1.y;                          \
        a4f += (E) * f2.x; a5f += (E) * f2.y;                          \
        a6f += (E) * f3.x; a7f += (E) * f3.y;                          \
    } while (0)

__global__ void __launch_bounds__(256) gather_kernel(float* __restrict__ out,
                                                     const float* __restrict__ bias) {
    const int warp = threadIdx.x >> 5;
    const int dst  = blockIdx.x * 8 + warp;
    const int lane = threadIdx.x & 31;
    const int head = lane >> 3;

    const int beg = g_start[dst];
    const int cnt = g_count[dst];
    const float adh = g_adst[dst * NH + head];

    float a0f = 0.f, a1f = 0.f, a2f = 0.f, a3f = 0.f;
    float a4f = 0.f, a5f = 0.f, a6f = 0.f, a7f = 0.f;
    float den = 0.f;

    const int4* __restrict__ xr = (const int4*)g_xh;   // 32 int4 per row
    const float* __restrict__ asr = g_asrc;

    int i = 0;
    for (; i + 8 <= cnt; i += 8) {
        int s[8];
#pragma unroll
        for (int j = 0; j < 8; j++) s[j] = g_csr[beg + i + j];
        int4 xv[8];
        float l[8];
#pragma unroll
        for (int j = 0; j < 8; j++) xv[j] = xr[(size_t)s[j] * 32 + lane];
#pragma unroll
        for (int j = 0; j < 8; j++) l[j] = asr[s[j] * NH + head];
#pragma unroll
        for (int j = 0; j < 8; j++) {
            float e = lrelu_exp(l[j] + adh);
            den += e;
            ACC_EDGE(xv[j], e);
        }
    }
    for (; i + 4 <= cnt; i += 4) {
        int s[4];
#pragma unroll
        for (int j = 0; j < 4; j++) s[j] = g_csr[beg + i + j];
        int4 xv[4];
        float l[4];
#pragma unroll
        for (int j = 0; j < 4; j++) xv[j] = xr[(size_t)s[j] * 32 + lane];
#pragma unroll
        for (int j = 0; j < 4; j++) l[j] = asr[s[j] * NH + head];
#pragma unroll
        for (int j = 0; j < 4; j++) {
            float e = lrelu_exp(l[j] + adh);
            den += e;
            ACC_EDGE(xv[j], e);
        }
    }
    for (; i < cnt; i++) {
        int s = g_csr[beg + i];
        int4 xv = xr[(size_t)s * 32 + lane];
        float e = lrelu_exp(asr[s * NH + head] + adh);
        den += e;
        ACC_EDGE(xv, e);
    }

    float r = 0.25f / den;
    a0f *= r; a1f *= r; a2f *= r; a3f *= r;
    a4f *= r; a5f *= r; a6f *= r; a7f *= r;

    // sum across the 4 heads (lane groups of 8)
#pragma unroll
    for (int off = 8; off <= 16; off <<= 1) {
        a0f += __shfl_xor_sync(0xffffffffu, a0f, off);
        a1f += __shfl_xor_sync(0xffffffffu, a1f, off);
        a2f += __shfl_xor_sync(0xffffffffu, a2f, off);
        a3f += __shfl_xor_sync(0xffffffffu, a3f, off);
        a4f += __shfl_xor_sync(0xffffffffu, a4f, off);
        a5f += __shfl_xor_sync(0xffffffffu, a5f, off);
        a6f += __shfl_xor_sync(0xffffffffu, a6f, off);
        a7f += __shfl_xor_sync(0xffffffffu, a7f, off);
    }

    if (lane < 8) {
        const float* bq = &bias[lane * 8];
        float4 o0 = make_float4(a0f + bq[0], a1f + bq[1], a2f + bq[2], a3f + bq[3]);
        float4 o1 = make_float4(a4f + bq[4], a5f + bq[5], a6f + bq[6], a7f + bq[7]);
        *(float4*)&out[(size_t)dst * OC + lane * 8]     = o0;
        *(float4*)&out[(size_t)dst * OC + lane * 8 + 4] = o1;
    }
}
#undef ACC_EDGE

// ---------------- launch ----------------------------------------
// GEMM runs on a side stream, overlapped with the CSR build (they are
// independent); event fork/join keeps the whole thing graph-capturable.
// Streams/events are created once on the first (uncaptured) call.
extern "C" void kernel_launch(void* const* d_in, const int* in_sizes, int n_in,
                              void* d_out, int out_size) {
    const float* feature    = (const float*)d_in[0];
    const void*  edge_index = d_in[1];
    const float* lin_w      = (const float*)d_in[2];
    const float* att_src    = (const float*)d_in[3];
    const float* att_dst    = (const float*)d_in[4];
    const float* bias       = (const float*)d_in[5];
    float*       out        = (float*)d_out;

    static cudaStream_t s2 = nullptr;
    static cudaEvent_t  evA = nullptr, evB = nullptr;
    if (s2 == nullptr) {
        cudaStreamCreateWithFlags(&s2, cudaStreamNonBlocking);
        cudaEventCreateWithFlags(&evA, cudaEventDisableTiming);
        cudaEventCreateWithFlags(&evB, cudaEventDisableTiming);
    }

    detect_kernel<<<1, 256>>>((const int*)edge_index);
    zero_kernel<<<(NPAD + 255) / 256, 256>>>();

    // fork: GEMM on s2, CSR build on the main stream
    cudaEventRecord(evA, 0);
    cudaStreamWaitEvent(s2, evA, 0);

    dim3 ggrid((NN + 127) / 128, NH);
    gemm_kernel<<<ggrid, 256, 0, s2>>>(feature, lin_w, att_src, att_dst);

    hist_kernel<<<(NET + 1023) / 1024, 256>>>(edge_index);
    scan1_kernel<<<NBLK, SCAN_BLK>>>();
    scan2_kernel<<<1, 64>>>();
    scan3_kernel<<<(NPAD + 255) / 256, 256>>>();
    fill_kernel<<<(NET + 1023) / 1024, 256>>>(edge_index);

    // join
    cudaEventRecord(evB, s2);
    cudaStreamWaitEvent(0, evB, 0);

    gather_kernel<<<NN / 8, 256>>>(out, bias);
}